// round 1
// baseline (speedup 1.0000x reference)
#include <cuda_runtime.h>
#include <math.h>

#define QLEN  1024
#define KLEN  1024
#define RLEN  2048
#define NPRED 256
#define BSZ   4
#define NH    16
#define DH    64
#define DM    1024
#define DI    4096
#define NB    (BSZ*NH)   /* 64 head-batches */

// ---------------------------------------------------------------------------
// Scratch (device globals; allocation in kernel_launch is forbidden)
// ---------------------------------------------------------------------------
__device__ float g_KH [QLEN*BSZ*DM];     // k_head_h  [i,b,n,d]
__device__ float g_VH [QLEN*BSZ*DM];     // v_head_h
__device__ float g_KR [RLEN*BSZ*DM];     // k_head_r  [jr,b,n,d]
__device__ float g_QT [QLEN*BSZ*DM];     // q proj temp (h) / QG2 (g)
__device__ float g_QW [QLEN*BSZ*DM];     // q + r_w_bias
__device__ float g_QR [QLEN*BSZ*DM];     // q + r_r_bias
__device__ float g_QG [NPRED*BSZ*DM];    // g-stream q before target mapping
__device__ float g_AC [(long)NB*QLEN*KLEN];   // AC scores, then P (in-place)
__device__ float g_BD [(long)NB*QLEN*RLEN];   // BD scores (full 2048 wide)
__device__ float g_AV [QLEN*BSZ*DM];     // attn_vec [i/l, b, n, d]
__device__ float g_AV2[NPRED*BSZ*DM];    // g attn_vec mapped back [m,b,n,d]
__device__ float g_ATTH[QLEN*BSZ*DM];    // post-attention LN output (h)
__device__ float g_ATTG[NPRED*BSZ*DM];   // post-attention LN output (g)
__device__ float g_FF1[QLEN*BSZ*DI];     // FF hidden
__device__ float g_FF2[QLEN*BSZ*DM];     // FF output pre-LN

// ---------------------------------------------------------------------------
// Generic strided batched SGEMM:
//   C[z][i][j] = sum_k A[z*bsA + i*ldaI + k*ldaK] * B[z*bsB + k*ldbK + j*ldbJ]
//   C element at  C + z*bsC + i*ldcI + j   (inner C stride always 1)
//   Optional per-column bias and exact GELU epilogue.
// Tiles: 64x64, 256 threads, 4x4 micro, BK=16.
// ---------------------------------------------------------------------------
__global__ void bgemm(const float* __restrict__ A, const float* __restrict__ B,
                      float* __restrict__ C,
                      int M, int N, int K,
                      long ldaI, long ldaK, long bsA,
                      long ldbK, long ldbJ, long bsB,
                      long ldcI, long bsC,
                      const float* __restrict__ bias, int act)
{
    __shared__ float As[16][64];
    __shared__ float Bs[16][64];

    const int z  = blockIdx.z;
    const float* Ab = A + (long)z * bsA;
    const float* Bb = B + (long)z * bsB;
    float*       Cb = C + (long)z * bsC;

    const int i0 = blockIdx.y * 64;
    const int j0 = blockIdx.x * 64;
    const int tid = threadIdx.x;
    const int tx = tid & 15;      // j-dim
    const int ty = tid >> 4;      // i-dim

    const bool ak1 = (ldaK == 1);
    const bool bj1 = (ldbJ == 1);

    float acc[4][4];
#pragma unroll
    for (int r = 0; r < 4; r++)
#pragma unroll
        for (int c = 0; c < 4; c++) acc[r][c] = 0.0f;

    for (int k0 = 0; k0 < K; k0 += 16) {
        // --- load A tile (64 x 16) ---
        for (int e = tid; e < 1024; e += 256) {
            int i, k;
            if (ak1) { k = e & 15; i = e >> 4; }
            else     { i = e & 63; k = e >> 6; }
            int gi = i0 + i, gk = k0 + k;
            float v = 0.0f;
            if (gi < M && gk < K) v = Ab[(long)gi * ldaI + (long)gk * ldaK];
            As[k][i] = v;
        }
        // --- load B tile (16 x 64) ---
        for (int e = tid; e < 1024; e += 256) {
            int j, k;
            if (bj1) { j = e & 63; k = e >> 6; }
            else     { k = e & 15; j = e >> 4; }
            int gj = j0 + j, gk = k0 + k;
            float v = 0.0f;
            if (gk < K && gj < N) v = Bb[(long)gk * ldbK + (long)gj * ldbJ];
            Bs[k][j] = v;
        }
        __syncthreads();

#pragma unroll
        for (int kk = 0; kk < 16; kk++) {
            float4 a4 = *(const float4*)&As[kk][ty * 4];
            float4 b4 = *(const float4*)&Bs[kk][tx * 4];
            float a[4] = {a4.x, a4.y, a4.z, a4.w};
            float b[4] = {b4.x, b4.y, b4.z, b4.w};
#pragma unroll
            for (int r = 0; r < 4; r++)
#pragma unroll
                for (int c = 0; c < 4; c++)
                    acc[r][c] = fmaf(a[r], b[c], acc[r][c]);
        }
        __syncthreads();
    }

#pragma unroll
    for (int r = 0; r < 4; r++) {
        int gi = i0 + ty * 4 + r;
        if (gi >= M) continue;
#pragma unroll
        for (int c = 0; c < 4; c++) {
            int gj = j0 + tx * 4 + c;
            if (gj >= N) continue;
            float v = acc[r][c];
            if (bias) v += bias[gj];
            if (act)  v = 0.5f * v * (1.0f + erff(v * 0.70710678118654752f));
            Cb[(long)gi * ldcI + gj] = v;
        }
    }
}

// ---------------------------------------------------------------------------
// QW = QT + r_w_bias(col), QR = QT + r_r_bias(col); col = idx % 1024 = (n,d)
// ---------------------------------------------------------------------------
__global__ void add_bias2(const float* __restrict__ src,
                          const float* __restrict__ bw,   // r_w_bias flat [1024]
                          const float* __restrict__ br,   // r_r_bias flat [1024]
                          float* __restrict__ dw, float* __restrict__ dr, long n)
{
    long idx = (long)blockIdx.x * blockDim.x + threadIdx.x;
    long stride = (long)gridDim.x * blockDim.x;
    for (; idx < n; idx += stride) {
        int c = (int)(idx & (DM - 1));
        float v = src[idx];
        dw[idx] = v + bw[c];
        dr[idx] = v + br[c];
    }
}

// ---------------------------------------------------------------------------
// Softmax with relative shift gather:
//   P[z,i,j] = softmax_j( (AC[z,i,j] + BD[z,i,j-i+KLEN]) * 0.125 - 1e30*mask[i,j,b] )
// One block per (i, z); 256 threads, 4 elems each. Writes in place over AC.
// ---------------------------------------------------------------------------
__global__ void softmax_shift(const float* __restrict__ AC,
                              const float* __restrict__ BD,
                              const float* __restrict__ mask,
                              float* __restrict__ P)
{
    const int i = blockIdx.x;          // 0..QLEN-1
    const int z = blockIdx.y;          // 0..NB-1
    const int b = z >> 4;
    const float* ac = AC + ((long)z * QLEN + i) * KLEN;
    const float* bd = BD + ((long)z * QLEN + i) * RLEN;
    float*       p  = P  + ((long)z * QLEN + i) * KLEN;

    __shared__ float red[256];
    const int tid = threadIdx.x;

    float vals[4];
    float lm = -1e38f;
#pragma unroll
    for (int r = 0; r < 4; r++) {
        int j = tid + r * 256;
        float s = (ac[j] + bd[j - i + KLEN]) * 0.125f
                - 1e30f * mask[((long)i * KLEN + j) * BSZ + b];
        vals[r] = s;
        lm = fmaxf(lm, s);
    }
    red[tid] = lm; __syncthreads();
    for (int s = 128; s > 0; s >>= 1) {
        if (tid < s) red[tid] = fmaxf(red[tid], red[tid + s]);
        __syncthreads();
    }
    float mx = red[0]; __syncthreads();

    float ls = 0.0f;
#pragma unroll
    for (int r = 0; r < 4; r++) {
        vals[r] = expf(vals[r] - mx);
        ls += vals[r];
    }
    red[tid] = ls; __syncthreads();
    for (int s = 128; s > 0; s >>= 1) {
        if (tid < s) red[tid] += red[tid + s];
        __syncthreads();
    }
    float inv = 1.0f / red[0];
#pragma unroll
    for (int r = 0; r < 4; r++)
        p[tid + r * 256] = vals[r] * inv;
}

// ---------------------------------------------------------------------------
// out = LayerNorm(x + res) * scale + bias, D = 1024, one block per row
// ---------------------------------------------------------------------------
__global__ void ln_res(const float* __restrict__ x, const float* __restrict__ res,
                       const float* __restrict__ sc, const float* __restrict__ bi,
                       float* __restrict__ out)
{
    const long row = blockIdx.x;
    const float* xr = x   + row * DM;
    const float* rr = res + row * DM;
    float*       o  = out + row * DM;
    const int tid = threadIdx.x;

    __shared__ float red[256];

    float v[4];
    float s = 0.0f;
#pragma unroll
    for (int r = 0; r < 4; r++) {
        int c = tid + r * 256;
        v[r] = xr[c] + rr[c];
        s += v[r];
    }
    red[tid] = s; __syncthreads();
    for (int st = 128; st > 0; st >>= 1) {
        if (tid < st) red[tid] += red[tid + st];
        __syncthreads();
    }
    float mean = red[0] * (1.0f / DM); __syncthreads();

    float sq = 0.0f;
#pragma unroll
    for (int r = 0; r < 4; r++) {
        float d = v[r] - mean;
        sq += d * d;
    }
    red[tid] = sq; __syncthreads();
    for (int st = 128; st > 0; st >>= 1) {
        if (tid < st) red[tid] += red[tid + st];
        __syncthreads();
    }
    float rstd = rsqrtf(red[0] * (1.0f / DM) + 1e-8f);
#pragma unroll
    for (int r = 0; r < 4; r++) {
        int c = tid + r * 256;
        o[c] = (v[r] - mean) * rstd * sc[c] + bi[c];
    }
}

// ---------------------------------------------------------------------------
static inline dim3 ggrid(int M, int N, int nb)
{
    return dim3((N + 63) / 64, (M + 63) / 64, nb);
}

extern "C" void kernel_launch(void* const* d_in, const int* in_sizes, int n_in,
                              void* d_out, int out_size)
{
    const float* Xh  = (const float*)d_in[0];
    const float* Xg  = (const float*)d_in[1];
    const float* mh  = (const float*)d_in[2];
    const float* mg  = (const float*)d_in[3];
    const float* R   = (const float*)d_in[4];
    const float* TM  = (const float*)d_in[5];
    const float* qw  = (const float*)d_in[6];
    const float* kw  = (const float*)d_in[7];
    const float* vw  = (const float*)d_in[8];
    const float* rw  = (const float*)d_in[9];
    const float* rrb = (const float*)d_in[10];  // r_r_bias
    const float* rwb = (const float*)d_in[11];  // r_w_bias
    const float* lns = (const float*)d_in[12];
    const float* lnb = (const float*)d_in[13];
    const float* w1  = (const float*)d_in[14];
    const float* b1  = (const float*)d_in[15];
    const float* w2  = (const float*)d_in[16];
    const float* b2  = (const float*)d_in[17];
    const float* fls = (const float*)d_in[18];
    const float* flb = (const float*)d_in[19];
    float* out = (float*)d_out;

    float *KH, *VH, *KR, *QT, *QW, *QR, *QG, *AC, *BD, *AV, *AV2,
          *ATTH, *ATTG, *FF1, *FF2;
    cudaGetSymbolAddress((void**)&KH,  g_KH);
    cudaGetSymbolAddress((void**)&VH,  g_VH);
    cudaGetSymbolAddress((void**)&KR,  g_KR);
    cudaGetSymbolAddress((void**)&QT,  g_QT);
    cudaGetSymbolAddress((void**)&QW,  g_QW);
    cudaGetSymbolAddress((void**)&QR,  g_QR);
    cudaGetSymbolAddress((void**)&QG,  g_QG);
    cudaGetSymbolAddress((void**)&AC,  g_AC);
    cudaGetSymbolAddress((void**)&BD,  g_BD);
    cudaGetSymbolAddress((void**)&AV,  g_AV);
    cudaGetSymbolAddress((void**)&AV2, g_AV2);
    cudaGetSymbolAddress((void**)&ATTH, g_ATTH);
    cudaGetSymbolAddress((void**)&ATTG, g_ATTG);
    cudaGetSymbolAddress((void**)&FF1, g_FF1);
    cudaGetSymbolAddress((void**)&FF2, g_FF2);

    const int T = 256;
    const int MH = QLEN * BSZ;     // 4096 rows (i,b)
    const int MG = NPRED * BSZ;    // 1024 rows (m,b)

    // ---- shared projections ----
    bgemm<<<ggrid(MH, DM, 1), T>>>(Xh, kw, KH, MH, DM, DM,
                                   DM, 1, 0,  DM, 1, 0,  DM, 0, nullptr, 0);
    bgemm<<<ggrid(MH, DM, 1), T>>>(Xh, vw, VH, MH, DM, DM,
                                   DM, 1, 0,  DM, 1, 0,  DM, 0, nullptr, 0);
    bgemm<<<ggrid(RLEN*BSZ, DM, 1), T>>>(R, rw, KR, RLEN*BSZ, DM, DM,
                                   DM, 1, 0,  DM, 1, 0,  DM, 0, nullptr, 0);

    // ================= h-stream =================
    bgemm<<<ggrid(MH, DM, 1), T>>>(Xh, qw, QT, MH, DM, DM,
                                   DM, 1, 0,  DM, 1, 0,  DM, 0, nullptr, 0);
    add_bias2<<<4096, T>>>(QT, rwb, rrb, QW, QR, (long)MH * DM);

    // AC[z,i,j] = (q+rw_bias)·k   (batched NT over z = b*16+n, head base = 64*z)
    bgemm<<<ggrid(QLEN, KLEN, NB), T>>>(QW, KH, AC, QLEN, KLEN, DH,
                                   4096, 1, 64,   1, 4096, 64,
                                   KLEN, (long)QLEN * KLEN, nullptr, 0);
    // BD[z,i,jr] = (q+rr_bias)·kr  (full 2048 wide; shift handled in softmax)
    bgemm<<<ggrid(QLEN, RLEN, NB), T>>>(QR, KR, BD, QLEN, RLEN, DH,
                                   4096, 1, 64,   1, 4096, 64,
                                   RLEN, (long)QLEN * RLEN, nullptr, 0);
    softmax_shift<<<dim3(QLEN, NB), T>>>(AC, BD, mh, AC);
    // attn_vec = P @ V  -> [i,b,n,d]
    bgemm<<<ggrid(QLEN, DH, NB), T>>>(AC, VH, AV, QLEN, DH, KLEN,
                                   KLEN, 1, (long)QLEN * KLEN,
                                   4096, 1, 64,   4096, 64, nullptr, 0);
    ln_res<<<MH, T>>>(AV, Xh, lns, lnb, ATTH);

    // ================= g-stream =================
    bgemm<<<ggrid(MG, DM, 1), T>>>(Xg, qw, QG, MG, DM, DM,
                                   DM, 1, 0,  DM, 1, 0,  DM, 0, nullptr, 0);
    // QG2[l,b,nd] = sum_m TM[m,l,b] * QG[m,b,nd]  (batch over b)
    bgemm<<<ggrid(QLEN, DM, BSZ), T>>>(TM, QG, QT, QLEN, DM, NPRED,
                                   4, 4096, 1,   4096, 1, DM,
                                   4096, DM, nullptr, 0);
    add_bias2<<<4096, T>>>(QT, rwb, rrb, QW, QR, (long)MH * DM);

    bgemm<<<ggrid(QLEN, KLEN, NB), T>>>(QW, KH, AC, QLEN, KLEN, DH,
                                   4096, 1, 64,   1, 4096, 64,
                                   KLEN, (long)QLEN * KLEN, nullptr, 0);
    bgemm<<<ggrid(QLEN, RLEN, NB), T>>>(QR, KR, BD, QLEN, RLEN, DH,
                                   4096, 1, 64,   1, 4096, 64,
                                   RLEN, (long)QLEN * RLEN, nullptr, 0);
    softmax_shift<<<dim3(QLEN, NB), T>>>(AC, BD, mg, AC);
    bgemm<<<ggrid(QLEN, DH, NB), T>>>(AC, VH, AV, QLEN, DH, KLEN,
                                   KLEN, 1, (long)QLEN * KLEN,
                                   4096, 1, 64,   4096, 64, nullptr, 0);
    // map back: AV2[m,b,nd] = sum_l TM[m,l,b] * AV[l,b,nd]  (batch over b)
    bgemm<<<ggrid(NPRED, DM, BSZ), T>>>(TM, AV, AV2, NPRED, DM, QLEN,
                                   4096, 4, 1,   4096, 1, DM,
                                   4096, DM, nullptr, 0);
    ln_res<<<MG, T>>>(AV2, Xg, lns, lnb, ATTG);

    // ================= FFN (h) =================
    bgemm<<<ggrid(MH, DI, 1), T>>>(ATTH, w1, FF1, MH, DI, DM,
                                   DM, 1, 0,  DI, 1, 0,  DI, 0, b1, 1);
    bgemm<<<ggrid(MH, DM, 1), T>>>(FF1, w2, FF2, MH, DM, DI,
                                   DI, 1, 0,  DM, 1, 0,  DM, 0, b2, 0);
    ln_res<<<MH, T>>>(FF2, ATTH, fls, flb, out);

    // ================= FFN (g) =================
    bgemm<<<ggrid(MG, DI, 1), T>>>(ATTG, w1, FF1, MG, DI, DM,
                                   DM, 1, 0,  DI, 1, 0,  DI, 0, b1, 1);
    bgemm<<<ggrid(MG, DM, 1), T>>>(FF1, w2, FF2, MG, DM, DI,
                                   DI, 1, 0,  DM, 1, 0,  DM, 0, b2, 0);
    ln_res<<<MG, T>>>(FF2, ATTG, fls, flb, out + (long)MH * DM);
}

// round 3
// speedup vs baseline: 2.6896x; 2.6896x over previous
#include <cuda_runtime.h>
#include <cstdint>
#include <math.h>

#define QLEN  1024
#define KLEN  1024
#define RLEN  2048
#define NPRED 256
#define BSZ   4
#define NH    16
#define DH    64
#define DM    1024
#define DI    4096
#define NB    (BSZ*NH)   /* 64 head-batches */

typedef unsigned int u32;

// ---------------------------------------------------------------------------
// Scratch (device globals; allocation in kernel_launch is forbidden)
// ---------------------------------------------------------------------------
__device__ float g_KH [QLEN*BSZ*DM];     // k_head_h  [i,b,n,d]
__device__ float g_VH [QLEN*BSZ*DM];     // v_head_h
__device__ float g_KR [RLEN*BSZ*DM];     // k_head_r  [jr,b,n,d]
__device__ float g_QT [QLEN*BSZ*DM];     // q proj temp (h) / QG2 (g)
__device__ float g_QW [QLEN*BSZ*DM];     // q + r_w_bias
__device__ float g_QR [QLEN*BSZ*DM];     // q + r_r_bias
__device__ float g_QG [NPRED*BSZ*DM];    // g-stream q before target mapping
__device__ float g_AC [(long)NB*QLEN*KLEN];   // AC scores, then P (in-place)
__device__ float g_BD [(long)NB*QLEN*RLEN];   // BD scores (full 2048 wide)
__device__ float g_AV [QLEN*BSZ*DM];     // attn_vec [i/l, b, n, d]
__device__ float g_AV2[NPRED*BSZ*DM];    // g attn_vec mapped back [m,b,n,d]
__device__ float g_ATTH[QLEN*BSZ*DM];    // post-attention LN output (h)
__device__ float g_ATTG[NPRED*BSZ*DM];   // post-attention LN output (g)
__device__ float g_FF1[QLEN*BSZ*DI];     // FF hidden
__device__ float g_FF2[QLEN*BSZ*DM];     // FF output pre-LN

// ---------------------------------------------------------------------------
__device__ __forceinline__ u32 f2tf32(float v)
{
    u32 r;
    asm("cvt.rna.tf32.f32 %0, %1;" : "=r"(r) : "f"(v));
    return r;
}

__device__ __forceinline__ void mma_tf32(float* c, const u32* a, const u32* b)
{
    asm volatile(
        "mma.sync.aligned.m16n8k8.row.col.f32.tf32.tf32.f32 "
        "{%0,%1,%2,%3}, {%4,%5,%6,%7}, {%8,%9}, {%0,%1,%2,%3};\n"
        : "+f"(c[0]), "+f"(c[1]), "+f"(c[2]), "+f"(c[3])
        : "r"(a[0]), "r"(a[1]), "r"(a[2]), "r"(a[3]), "r"(b[0]), "r"(b[1]));
}

// ---------------------------------------------------------------------------
// Tensor-core strided batched GEMM (tf32, fp32 accumulate):
//   C[z][i][j] = sum_k A[z*bsA + i*ldaI + k*ldaK] * B[z*bsB + k*ldbK + j*ldbJ]
// Block tile 128x64, BK=16, 8 warps (4x2), each warp 32x32 via m16n8k8.
// Double-buffered smem with register staging. Optional bias + exact GELU.
// ---------------------------------------------------------------------------
#define BM 128
#define BN 64
#define BKT 16

__global__ __launch_bounds__(256) void bgemm_tc(
    const float* __restrict__ A, const float* __restrict__ B,
    float* __restrict__ C,
    int M, int N, int K,
    long ldaI, long ldaK, long bsA,
    long ldbK, long ldbJ, long bsB,
    long ldcI, long bsC,
    const float* __restrict__ bias, int act)
{
    __shared__ u32 As[2][BM][BKT + 1];
    __shared__ u32 Bs[2][BN][BKT + 1];

    const int z = blockIdx.z;
    const float* Ab = A + (long)z * bsA;
    const float* Bb = B + (long)z * bsB;
    float*       Cb = C + (long)z * bsC;

    const int i0 = blockIdx.y * BM;
    const int j0 = blockIdx.x * BN;
    const int tid  = threadIdx.x;
    const int warp = tid >> 5;
    const int lane = tid & 31;
    const int g = lane >> 2;      // group id (0..7)
    const int t = lane & 3;       // thread-in-group (0..3)
    const int wm = (warp & 3) * 32;   // warp M offset within block
    const int wn = (warp >> 2) * 32;  // warp N offset within block

    const bool ak1 = (ldaK == 1);
    const bool bj1 = (ldbJ == 1);

    float acc[2][4][4];
#pragma unroll
    for (int mt = 0; mt < 2; mt++)
#pragma unroll
        for (int nt = 0; nt < 4; nt++)
#pragma unroll
            for (int e = 0; e < 4; e++) acc[mt][nt][e] = 0.0f;

    float ra[8], rb[4];

    // stage tile (global -> regs)
    auto stage = [&](int k0) {
#pragma unroll
        for (int u = 0; u < 8; u++) {
            int e = tid + u * 256;
            int i, k;
            if (ak1) { k = e & 15; i = e >> 4; }
            else     { i = e & 127; k = e >> 7; }
            int gi = i0 + i, gk = k0 + k;
            ra[u] = (gi < M && gk < K) ? Ab[(long)gi * ldaI + (long)gk * ldaK] : 0.0f;
        }
#pragma unroll
        for (int u = 0; u < 4; u++) {
            int e = tid + u * 256;
            int n, k;
            if (bj1) { n = e & 63; k = e >> 6; }
            else     { k = e & 15; n = e >> 4; }
            int gn = j0 + n, gk = k0 + k;
            rb[u] = (gn < N && gk < K) ? Bb[(long)gk * ldbK + (long)gn * ldbJ] : 0.0f;
        }
    };
    // commit regs -> smem (as tf32 bit patterns)
    auto commit = [&](int buf) {
#pragma unroll
        for (int u = 0; u < 8; u++) {
            int e = tid + u * 256;
            int i, k;
            if (ak1) { k = e & 15; i = e >> 4; }
            else     { i = e & 127; k = e >> 7; }
            As[buf][i][k] = f2tf32(ra[u]);
        }
#pragma unroll
        for (int u = 0; u < 4; u++) {
            int e = tid + u * 256;
            int n, k;
            if (bj1) { n = e & 63; k = e >> 6; }
            else     { k = e & 15; n = e >> 4; }
            Bs[buf][n][k] = f2tf32(rb[u]);
        }
    };

    stage(0);
    commit(0);
    __syncthreads();

    int buf = 0;
    for (int k0 = 0; k0 < K; k0 += BKT) {
        const bool more = (k0 + BKT) < K;
        if (more) stage(k0 + BKT);

#pragma unroll
        for (int kk = 0; kk < 2; kk++) {
            const int ks = kk * 8;
            u32 af[2][4], bf[4][2];
#pragma unroll
            for (int mt = 0; mt < 2; mt++) {
                int r = wm + mt * 16;
                af[mt][0] = As[buf][r + g    ][ks + t];
                af[mt][1] = As[buf][r + g + 8][ks + t];
                af[mt][2] = As[buf][r + g    ][ks + t + 4];
                af[mt][3] = As[buf][r + g + 8][ks + t + 4];
            }
#pragma unroll
            for (int nt = 0; nt < 4; nt++) {
                int c = wn + nt * 8;
                bf[nt][0] = Bs[buf][c + g][ks + t];
                bf[nt][1] = Bs[buf][c + g][ks + t + 4];
            }
#pragma unroll
            for (int mt = 0; mt < 2; mt++)
#pragma unroll
                for (int nt = 0; nt < 4; nt++)
                    mma_tf32(acc[mt][nt], af[mt], bf[nt]);
        }

        if (more) {
            commit(buf ^ 1);
            __syncthreads();
            buf ^= 1;
        }
    }

    // epilogue
#pragma unroll
    for (int mt = 0; mt < 2; mt++) {
#pragma unroll
        for (int nt = 0; nt < 4; nt++) {
            int col = j0 + wn + nt * 8 + t * 2;
            if (col >= N) continue;
            float b0 = 0.0f, b1 = 0.0f;
            if (bias) { b0 = bias[col]; b1 = bias[col + 1]; }
#pragma unroll
            for (int half = 0; half < 2; half++) {
                int row = i0 + wm + mt * 16 + g + half * 8;
                if (row >= M) continue;
                float v0 = acc[mt][nt][half * 2 + 0] + b0;
                float v1 = acc[mt][nt][half * 2 + 1] + b1;
                if (act) {
                    v0 = 0.5f * v0 * (1.0f + erff(v0 * 0.70710678118654752f));
                    v1 = 0.5f * v1 * (1.0f + erff(v1 * 0.70710678118654752f));
                }
                float2 vv = make_float2(v0, v1);
                *(float2*)&Cb[(long)row * ldcI + col] = vv;
            }
        }
    }
}

// ---------------------------------------------------------------------------
// QW = QT + r_w_bias(col), QR = QT + r_r_bias(col); col = idx % 1024 = (n,d)
// ---------------------------------------------------------------------------
__global__ void add_bias2(const float* __restrict__ src,
                          const float* __restrict__ bw,
                          const float* __restrict__ br,
                          float* __restrict__ dw, float* __restrict__ dr, long n)
{
    long idx = (long)blockIdx.x * blockDim.x + threadIdx.x;
    long stride = (long)gridDim.x * blockDim.x;
    for (; idx < n; idx += stride) {
        int c = (int)(idx & (DM - 1));
        float v = src[idx];
        dw[idx] = v + bw[c];
        dr[idx] = v + br[c];
    }
}

// ---------------------------------------------------------------------------
// Softmax with relative shift gather:
//   P[z,i,j] = softmax_j( (AC[z,i,j] + BD[z,i,j-i+KLEN]) * 0.125 - 1e30*mask[i,j,b] )
// ---------------------------------------------------------------------------
__global__ void softmax_shift(const float* __restrict__ AC,
                              const float* __restrict__ BD,
                              const float* __restrict__ mask,
                              float* __restrict__ P)
{
    const int i = blockIdx.x;
    const int z = blockIdx.y;
    const int b = z >> 4;
    const float* ac = AC + ((long)z * QLEN + i) * KLEN;
    const float* bd = BD + ((long)z * QLEN + i) * RLEN;
    float*       p  = P  + ((long)z * QLEN + i) * KLEN;

    __shared__ float red[256];
    const int tid = threadIdx.x;

    float vals[4];
    float lm = -1e38f;
#pragma unroll
    for (int r = 0; r < 4; r++) {
        int j = tid + r * 256;
        float s = (ac[j] + bd[j - i + KLEN]) * 0.125f
                - 1e30f * mask[((long)i * KLEN + j) * BSZ + b];
        vals[r] = s;
        lm = fmaxf(lm, s);
    }
    red[tid] = lm; __syncthreads();
    for (int s = 128; s > 0; s >>= 1) {
        if (tid < s) red[tid] = fmaxf(red[tid], red[tid + s]);
        __syncthreads();
    }
    float mx = red[0]; __syncthreads();

    float ls = 0.0f;
#pragma unroll
    for (int r = 0; r < 4; r++) {
        vals[r] = expf(vals[r] - mx);
        ls += vals[r];
    }
    red[tid] = ls; __syncthreads();
    for (int s = 128; s > 0; s >>= 1) {
        if (tid < s) red[tid] += red[tid + s];
        __syncthreads();
    }
    float inv = 1.0f / red[0];
#pragma unroll
    for (int r = 0; r < 4; r++)
        p[tid + r * 256] = vals[r] * inv;
}

// ---------------------------------------------------------------------------
// out = LayerNorm(x + res) * scale + bias, D = 1024, one block per row
// ---------------------------------------------------------------------------
__global__ void ln_res(const float* __restrict__ x, const float* __restrict__ res,
                       const float* __restrict__ sc, const float* __restrict__ bi,
                       float* __restrict__ out)
{
    const long row = blockIdx.x;
    const float* xr = x   + row * DM;
    const float* rr = res + row * DM;
    float*       o  = out + row * DM;
    const int tid = threadIdx.x;

    __shared__ float red[256];

    float v[4];
    float s = 0.0f;
#pragma unroll
    for (int r = 0; r < 4; r++) {
        int c = tid + r * 256;
        v[r] = xr[c] + rr[c];
        s += v[r];
    }
    red[tid] = s; __syncthreads();
    for (int st = 128; st > 0; st >>= 1) {
        if (tid < st) red[tid] += red[tid + st];
        __syncthreads();
    }
    float mean = red[0] * (1.0f / DM); __syncthreads();

    float sq = 0.0f;
#pragma unroll
    for (int r = 0; r < 4; r++) {
        float d = v[r] - mean;
        sq += d * d;
    }
    red[tid] = sq; __syncthreads();
    for (int st = 128; st > 0; st >>= 1) {
        if (tid < st) red[tid] += red[tid + st];
        __syncthreads();
    }
    float rstd = rsqrtf(red[0] * (1.0f / DM) + 1e-8f);
#pragma unroll
    for (int r = 0; r < 4; r++) {
        int c = tid + r * 256;
        o[c] = (v[r] - mean) * rstd * sc[c] + bi[c];
    }
}

// ---------------------------------------------------------------------------
static inline dim3 ggrid(int M, int N, int nb)
{
    return dim3((N + BN - 1) / BN, (M + BM - 1) / BM, nb);
}

extern "C" void kernel_launch(void* const* d_in, const int* in_sizes, int n_in,
                              void* d_out, int out_size)
{
    const float* Xh  = (const float*)d_in[0];
    const float* Xg  = (const float*)d_in[1];
    const float* mh  = (const float*)d_in[2];
    const float* mg  = (const float*)d_in[3];
    const float* R   = (const float*)d_in[4];
    const float* TM  = (const float*)d_in[5];
    const float* qw  = (const float*)d_in[6];
    const float* kw  = (const float*)d_in[7];
    const float* vw  = (const float*)d_in[8];
    const float* rw  = (const float*)d_in[9];
    const float* rrb = (const float*)d_in[10];
    const float* rwb = (const float*)d_in[11];
    const float* lns = (const float*)d_in[12];
    const float* lnb = (const float*)d_in[13];
    const float* w1  = (const float*)d_in[14];
    const float* b1  = (const float*)d_in[15];
    const float* w2  = (const float*)d_in[16];
    const float* b2  = (const float*)d_in[17];
    const float* fls = (const float*)d_in[18];
    const float* flb = (const float*)d_in[19];
    float* out = (float*)d_out;

    float *KH, *VH, *KR, *QT, *QW, *QR, *QG, *AC, *BD, *AV, *AV2,
          *ATTH, *ATTG, *FF1, *FF2;
    cudaGetSymbolAddress((void**)&KH,  g_KH);
    cudaGetSymbolAddress((void**)&VH,  g_VH);
    cudaGetSymbolAddress((void**)&KR,  g_KR);
    cudaGetSymbolAddress((void**)&QT,  g_QT);
    cudaGetSymbolAddress((void**)&QW,  g_QW);
    cudaGetSymbolAddress((void**)&QR,  g_QR);
    cudaGetSymbolAddress((void**)&QG,  g_QG);
    cudaGetSymbolAddress((void**)&AC,  g_AC);
    cudaGetSymbolAddress((void**)&BD,  g_BD);
    cudaGetSymbolAddress((void**)&AV,  g_AV);
    cudaGetSymbolAddress((void**)&AV2, g_AV2);
    cudaGetSymbolAddress((void**)&ATTH, g_ATTH);
    cudaGetSymbolAddress((void**)&ATTG, g_ATTG);
    cudaGetSymbolAddress((void**)&FF1, g_FF1);
    cudaGetSymbolAddress((void**)&FF2, g_FF2);

    const int T = 256;
    const int MH = QLEN * BSZ;     // 4096 rows (i,b)
    const int MG = NPRED * BSZ;    // 1024 rows (m,b)

    // ---- shared projections ----
    bgemm_tc<<<ggrid(MH, DM, 1), T>>>(Xh, kw, KH, MH, DM, DM,
                                   DM, 1, 0,  DM, 1, 0,  DM, 0, nullptr, 0);
    bgemm_tc<<<ggrid(MH, DM, 1), T>>>(Xh, vw, VH, MH, DM, DM,
                                   DM, 1, 0,  DM, 1, 0,  DM, 0, nullptr, 0);
    bgemm_tc<<<ggrid(RLEN*BSZ, DM, 1), T>>>(R, rw, KR, RLEN*BSZ, DM, DM,
                                   DM, 1, 0,  DM, 1, 0,  DM, 0, nullptr, 0);

    // ================= h-stream =================
    bgemm_tc<<<ggrid(MH, DM, 1), T>>>(Xh, qw, QT, MH, DM, DM,
                                   DM, 1, 0,  DM, 1, 0,  DM, 0, nullptr, 0);
    add_bias2<<<4096, T>>>(QT, rwb, rrb, QW, QR, (long)MH * DM);

    bgemm_tc<<<ggrid(QLEN, KLEN, NB), T>>>(QW, KH, AC, QLEN, KLEN, DH,
                                   4096, 1, 64,   1, 4096, 64,
                                   KLEN, (long)QLEN * KLEN, nullptr, 0);
    bgemm_tc<<<ggrid(QLEN, RLEN, NB), T>>>(QR, KR, BD, QLEN, RLEN, DH,
                                   4096, 1, 64,   1, 4096, 64,
                                   RLEN, (long)QLEN * RLEN, nullptr, 0);
    softmax_shift<<<dim3(QLEN, NB), T>>>(AC, BD, mh, AC);
    bgemm_tc<<<ggrid(QLEN, DH, NB), T>>>(AC, VH, AV, QLEN, DH, KLEN,
                                   KLEN, 1, (long)QLEN * KLEN,
                                   4096, 1, 64,   4096, 64, nullptr, 0);
    ln_res<<<MH, T>>>(AV, Xh, lns, lnb, ATTH);

    // ================= g-stream =================
    bgemm_tc<<<ggrid(MG, DM, 1), T>>>(Xg, qw, QG, MG, DM, DM,
                                   DM, 1, 0,  DM, 1, 0,  DM, 0, nullptr, 0);
    bgemm_tc<<<ggrid(QLEN, DM, BSZ), T>>>(TM, QG, QT, QLEN, DM, NPRED,
                                   4, 4096, 1,   4096, 1, DM,
                                   4096, DM, nullptr, 0);
    add_bias2<<<4096, T>>>(QT, rwb, rrb, QW, QR, (long)MH * DM);

    bgemm_tc<<<ggrid(QLEN, KLEN, NB), T>>>(QW, KH, AC, QLEN, KLEN, DH,
                                   4096, 1, 64,   1, 4096, 64,
                                   KLEN, (long)QLEN * KLEN, nullptr, 0);
    bgemm_tc<<<ggrid(QLEN, RLEN, NB), T>>>(QR, KR, BD, QLEN, RLEN, DH,
                                   4096, 1, 64,   1, 4096, 64,
                                   RLEN, (long)QLEN * RLEN, nullptr, 0);
    softmax_shift<<<dim3(QLEN, NB), T>>>(AC, BD, mg, AC);
    bgemm_tc<<<ggrid(QLEN, DH, NB), T>>>(AC, VH, AV, QLEN, DH, KLEN,
                                   KLEN, 1, (long)QLEN * KLEN,
                                   4096, 1, 64,   4096, 64, nullptr, 0);
    bgemm_tc<<<ggrid(NPRED, DM, BSZ), T>>>(TM, AV, AV2, NPRED, DM, QLEN,
                                   4096, 4, 1,   4096, 1, DM,
                                   4096, DM, nullptr, 0);
    ln_res<<<MG, T>>>(AV2, Xg, lns, lnb, ATTG);

    // ================= FFN (h) =================
    bgemm_tc<<<ggrid(MH, DI, 1), T>>>(ATTH, w1, FF1, MH, DI, DM,
                                   DM, 1, 0,  DI, 1, 0,  DI, 0, b1, 1);
    bgemm_tc<<<ggrid(MH, DM, 1), T>>>(FF1, w2, FF2, MH, DM, DI,
                                   DI, 1, 0,  DM, 1, 0,  DM, 0, b2, 0);
    ln_res<<<MH, T>>>(FF2, ATTH, fls, flb, out);

    // ================= FFN (g) =================
    bgemm_tc<<<ggrid(MG, DI, 1), T>>>(ATTG, w1, FF1, MG, DI, DM,
                                   DM, 1, 0,  DI, 1, 0,  DI, 0, b1, 1);
    bgemm_tc<<<ggrid(MG, DM, 1), T>>>(FF1, w2, FF2, MG, DM, DI,
                                   DI, 1, 0,  DM, 1, 0,  DM, 0, b2, 0);
    ln_res<<<MG, T>>>(FF2, ATTG, fls, flb, out + (long)MH * DM);
}

// round 4
// speedup vs baseline: 3.3991x; 1.2638x over previous
#include <cuda_runtime.h>
#include <cstdint>
#include <math.h>

#define QLEN  1024
#define KLEN  1024
#define RLEN  2048
#define NPRED 256
#define BSZ   4
#define NH    16
#define DH    64
#define DM    1024
#define DI    4096
#define NB    (BSZ*NH)   /* 64 head-batches */

typedef unsigned int u32;

// ---------------------------------------------------------------------------
// Scratch (device globals; allocation in kernel_launch is forbidden)
// ---------------------------------------------------------------------------
__device__ float g_KH [QLEN*BSZ*DM];
__device__ float g_VH [QLEN*BSZ*DM];
__device__ float g_KR [RLEN*BSZ*DM];
__device__ float g_QT [QLEN*BSZ*DM];
__device__ float g_QW [QLEN*BSZ*DM];
__device__ float g_QR [QLEN*BSZ*DM];
__device__ float g_QG [NPRED*BSZ*DM];
__device__ float g_AC [(long)NB*QLEN*KLEN];
__device__ float g_BD [(long)NB*QLEN*RLEN];
__device__ float g_AV [QLEN*BSZ*DM];
__device__ float g_AV2[NPRED*BSZ*DM];
__device__ float g_ATTH[QLEN*BSZ*DM];
__device__ float g_ATTG[NPRED*BSZ*DM];
__device__ float g_FF1[QLEN*BSZ*DI];
__device__ float g_FF2[QLEN*BSZ*DM];

// ---------------------------------------------------------------------------
__device__ __forceinline__ u32 f2tf32(float v)
{
    u32 r;
    asm("cvt.rna.tf32.f32 %0, %1;" : "=r"(r) : "f"(v));
    return r;
}

__device__ __forceinline__ void mma_tf32(float* c, const u32* a, const u32* b)
{
    asm volatile(
        "mma.sync.aligned.m16n8k8.row.col.f32.tf32.tf32.f32 "
        "{%0,%1,%2,%3}, {%4,%5,%6,%7}, {%8,%9}, {%0,%1,%2,%3};\n"
        : "+f"(c[0]), "+f"(c[1]), "+f"(c[2]), "+f"(c[3])
        : "r"(a[0]), "r"(a[1]), "r"(a[2]), "r"(a[3]), "r"(b[0]), "r"(b[1]));
}

// ===========================================================================
// FAST kernel. Requirements (all call sites satisfy):
//   ldaK == 1 (A k-contiguous), M % 128 == 0, K % 16 == 0, N % TBN == 0,
//   B either k-contiguous (ldbK==1) or n-contiguous (ldbJ==1),
//   all leading strides multiples of 4.
// Block tile: 128 x TBN, BK=16, 256 threads.
//   TBN=128: warps 2(M)x4(N), warp tile 64x32.
//   TBN=64 : warps 4(M)x2(N), warp tile 32x32.
// ===========================================================================
#define SK 20   /* smem row stride in u32: 80B -> 16B aligned quads, conflict-free frags */

template<int TBN>
__global__ __launch_bounds__(256, 2) void gemm_fast(
    const float* __restrict__ A, const float* __restrict__ B,
    float* __restrict__ C,
    int M, int N, int K,
    long ldaI, long bsA,
    long ldbK, long ldbJ, long bsB,
    long ldcI, long bsC,
    const float* __restrict__ bias, int act)
{
    constexpr int WARPS_M = (TBN == 128) ? 2 : 4;
    constexpr int WARPS_N = 8 / WARPS_M;
    constexpr int WROWS   = 128 / WARPS_M;   // 64 / 32
    constexpr int WCOLS   = TBN / WARPS_N;   // 32
    constexpr int MT      = WROWS / 16;      // 4 / 2
    constexpr int NT      = WCOLS / 8;       // 4
    constexpr int NBLD    = TBN / 64;        // 2 / 1

    __shared__ u32 As[2][128][SK];
    __shared__ u32 Bs[2][TBN][SK];

    const int z = blockIdx.z;
    const float* Ab = A + (long)z * bsA;
    const float* Bb = B + (long)z * bsB;
    float*       Cb = C + (long)z * bsC;

    const int i0 = blockIdx.y * 128;
    const int j0 = blockIdx.x * TBN;
    const int tid  = threadIdx.x;
    const int warp = tid >> 5;
    const int lane = tid & 31;
    const int g = lane >> 2;
    const int t = lane & 3;
    const int wm = (warp % WARPS_M) * WROWS;
    const int wn = (warp / WARPS_M) * WCOLS;

    // ---- A staging pointers (vector path, ldaK==1) ----
    const int arow = tid >> 2;            // 0..63
    const int aq4  = (tid & 3) * 4;
    const float* pA0 = Ab + (long)(i0 + arow) * ldaI + aq4;
    const float* pA1 = pA0 + (long)64 * ldaI;

    // ---- B staging pointers ----
    const bool btrans = (ldbJ == 1);      // uniform
    const float* pB[NBLD];
    int bx[NBLD], by[NBLD];               // commit coords
    long bstep;
    if (btrans) {
        bstep = 16 * ldbK;
#pragma unroll
        for (int u = 0; u < NBLD; u++) {
            int idx = tid + 256 * u;
            int nq = idx & (TBN / 4 - 1);
            int kk = idx / (TBN / 4);
            bx[u] = nq * 4; by[u] = kk;
            pB[u] = Bb + (long)kk * ldbK + (long)(j0 + nq * 4);
        }
    } else {
        bstep = 16;
#pragma unroll
        for (int u = 0; u < NBLD; u++) {
            int idx = tid + 256 * u;
            int nr = idx >> 2;
            int q4 = (idx & 3) * 4;
            bx[u] = nr; by[u] = q4;
            pB[u] = Bb + (long)(j0 + nr) * ldbJ + q4;
        }
    }

    float acc[MT][NT][4];
#pragma unroll
    for (int mt = 0; mt < MT; mt++)
#pragma unroll
        for (int nt = 0; nt < NT; nt++)
#pragma unroll
            for (int e = 0; e < 4; e++) acc[mt][nt][e] = 0.0f;

    float4 ra0, ra1, rb[NBLD];

    // prologue: load + commit tile 0
    ra0 = *(const float4*)pA0; pA0 += 16;
    ra1 = *(const float4*)pA1; pA1 += 16;
#pragma unroll
    for (int u = 0; u < NBLD; u++) { rb[u] = *(const float4*)pB[u]; pB[u] += bstep; }

    {
        uint4 w0 = make_uint4(f2tf32(ra0.x), f2tf32(ra0.y), f2tf32(ra0.z), f2tf32(ra0.w));
        *(uint4*)&As[0][arow][aq4] = w0;
        uint4 w1 = make_uint4(f2tf32(ra1.x), f2tf32(ra1.y), f2tf32(ra1.z), f2tf32(ra1.w));
        *(uint4*)&As[0][arow + 64][aq4] = w1;
        if (btrans) {
#pragma unroll
            for (int u = 0; u < NBLD; u++) {
                Bs[0][bx[u] + 0][by[u]] = f2tf32(rb[u].x);
                Bs[0][bx[u] + 1][by[u]] = f2tf32(rb[u].y);
                Bs[0][bx[u] + 2][by[u]] = f2tf32(rb[u].z);
                Bs[0][bx[u] + 3][by[u]] = f2tf32(rb[u].w);
            }
        } else {
#pragma unroll
            for (int u = 0; u < NBLD; u++) {
                uint4 w = make_uint4(f2tf32(rb[u].x), f2tf32(rb[u].y), f2tf32(rb[u].z), f2tf32(rb[u].w));
                *(uint4*)&Bs[0][bx[u]][by[u]] = w;
            }
        }
    }
    __syncthreads();

    const int nk = K >> 4;
    int buf = 0;
    for (int it = 0; it < nk; it++) {
        const bool more = (it + 1) < nk;
        if (more) {
            ra0 = *(const float4*)pA0; pA0 += 16;
            ra1 = *(const float4*)pA1; pA1 += 16;
#pragma unroll
            for (int u = 0; u < NBLD; u++) { rb[u] = *(const float4*)pB[u]; pB[u] += bstep; }
        }

#pragma unroll
        for (int kk = 0; kk < 2; kk++) {
            const int ks = kk * 8;
            u32 af[MT][4], bf[NT][2];
#pragma unroll
            for (int mt = 0; mt < MT; mt++) {
                int r = wm + mt * 16;
                af[mt][0] = As[buf][r + g    ][ks + t];
                af[mt][1] = As[buf][r + g + 8][ks + t];
                af[mt][2] = As[buf][r + g    ][ks + t + 4];
                af[mt][3] = As[buf][r + g + 8][ks + t + 4];
            }
#pragma unroll
            for (int nt = 0; nt < NT; nt++) {
                int c = wn + nt * 8;
                bf[nt][0] = Bs[buf][c + g][ks + t];
                bf[nt][1] = Bs[buf][c + g][ks + t + 4];
            }
#pragma unroll
            for (int mt = 0; mt < MT; mt++)
#pragma unroll
                for (int nt = 0; nt < NT; nt++)
                    mma_tf32(acc[mt][nt], af[mt], bf[nt]);
        }

        if (more) {
            int nb2 = buf ^ 1;
            uint4 w0 = make_uint4(f2tf32(ra0.x), f2tf32(ra0.y), f2tf32(ra0.z), f2tf32(ra0.w));
            *(uint4*)&As[nb2][arow][aq4] = w0;
            uint4 w1 = make_uint4(f2tf32(ra1.x), f2tf32(ra1.y), f2tf32(ra1.z), f2tf32(ra1.w));
            *(uint4*)&As[nb2][arow + 64][aq4] = w1;
            if (btrans) {
#pragma unroll
                for (int u = 0; u < NBLD; u++) {
                    Bs[nb2][bx[u] + 0][by[u]] = f2tf32(rb[u].x);
                    Bs[nb2][bx[u] + 1][by[u]] = f2tf32(rb[u].y);
                    Bs[nb2][bx[u] + 2][by[u]] = f2tf32(rb[u].z);
                    Bs[nb2][bx[u] + 3][by[u]] = f2tf32(rb[u].w);
                }
            } else {
#pragma unroll
                for (int u = 0; u < NBLD; u++) {
                    uint4 w = make_uint4(f2tf32(rb[u].x), f2tf32(rb[u].y), f2tf32(rb[u].z), f2tf32(rb[u].w));
                    *(uint4*)&Bs[nb2][bx[u]][by[u]] = w;
                }
            }
            __syncthreads();
            buf = nb2;
        }
    }

    // epilogue
#pragma unroll
    for (int mt = 0; mt < MT; mt++) {
#pragma unroll
        for (int nt = 0; nt < NT; nt++) {
            int col = j0 + wn + nt * 8 + t * 2;
            float b0 = 0.0f, b1 = 0.0f;
            if (bias) { b0 = bias[col]; b1 = bias[col + 1]; }
#pragma unroll
            for (int half = 0; half < 2; half++) {
                int row = i0 + wm + mt * 16 + g + half * 8;
                float v0 = acc[mt][nt][half * 2 + 0] + b0;
                float v1 = acc[mt][nt][half * 2 + 1] + b1;
                if (act) {
                    v0 = 0.5f * v0 * (1.0f + erff(v0 * 0.70710678118654752f));
                    v1 = 0.5f * v1 * (1.0f + erff(v1 * 0.70710678118654752f));
                }
                *(float2*)&Cb[(long)row * ldcI + col] = make_float2(v0, v1);
            }
        }
    }
}

// ===========================================================================
// Generic fallback (round-2 kernel) — used only for the two target-mapping
// GEMMs whose A operand has awkward strides. 128x64 tile, BK=16.
// ===========================================================================
#define BM 128
#define BN 64
#define BKT 16

__global__ __launch_bounds__(256) void bgemm_tc(
    const float* __restrict__ A, const float* __restrict__ B,
    float* __restrict__ C,
    int M, int N, int K,
    long ldaI, long ldaK, long bsA,
    long ldbK, long ldbJ, long bsB,
    long ldcI, long bsC,
    const float* __restrict__ bias, int act)
{
    __shared__ u32 As[2][BM][BKT + 1];
    __shared__ u32 Bs[2][BN][BKT + 1];

    const int z = blockIdx.z;
    const float* Ab = A + (long)z * bsA;
    const float* Bb = B + (long)z * bsB;
    float*       Cb = C + (long)z * bsC;

    const int i0 = blockIdx.y * BM;
    const int j0 = blockIdx.x * BN;
    const int tid  = threadIdx.x;
    const int warp = tid >> 5;
    const int lane = tid & 31;
    const int g = lane >> 2;
    const int t = lane & 3;
    const int wm = (warp & 3) * 32;
    const int wn = (warp >> 2) * 32;

    const bool ak1 = (ldaK == 1);
    const bool bj1 = (ldbJ == 1);

    float acc[2][4][4];
#pragma unroll
    for (int mt = 0; mt < 2; mt++)
#pragma unroll
        for (int nt = 0; nt < 4; nt++)
#pragma unroll
            for (int e = 0; e < 4; e++) acc[mt][nt][e] = 0.0f;

    float ra[8], rb[4];

    auto stage = [&](int k0) {
#pragma unroll
        for (int u = 0; u < 8; u++) {
            int e = tid + u * 256;
            int i, k;
            if (ak1) { k = e & 15; i = e >> 4; }
            else     { i = e & 127; k = e >> 7; }
            int gi = i0 + i, gk = k0 + k;
            ra[u] = (gi < M && gk < K) ? Ab[(long)gi * ldaI + (long)gk * ldaK] : 0.0f;
        }
#pragma unroll
        for (int u = 0; u < 4; u++) {
            int e = tid + u * 256;
            int n, k;
            if (bj1) { n = e & 63; k = e >> 6; }
            else     { k = e & 15; n = e >> 4; }
            int gn = j0 + n, gk = k0 + k;
            rb[u] = (gn < N && gk < K) ? Bb[(long)gk * ldbK + (long)gn * ldbJ] : 0.0f;
        }
    };
    auto commit = [&](int buf) {
#pragma unroll
        for (int u = 0; u < 8; u++) {
            int e = tid + u * 256;
            int i, k;
            if (ak1) { k = e & 15; i = e >> 4; }
            else     { i = e & 127; k = e >> 7; }
            As[buf][i][k] = f2tf32(ra[u]);
        }
#pragma unroll
        for (int u = 0; u < 4; u++) {
            int e = tid + u * 256;
            int n, k;
            if (bj1) { n = e & 63; k = e >> 6; }
            else     { k = e & 15; n = e >> 4; }
            Bs[buf][n][k] = f2tf32(rb[u]);
        }
    };

    stage(0);
    commit(0);
    __syncthreads();

    int buf = 0;
    for (int k0 = 0; k0 < K; k0 += BKT) {
        const bool more = (k0 + BKT) < K;
        if (more) stage(k0 + BKT);

#pragma unroll
        for (int kk = 0; kk < 2; kk++) {
            const int ks = kk * 8;
            u32 af[2][4], bf[4][2];
#pragma unroll
            for (int mt = 0; mt < 2; mt++) {
                int r = wm + mt * 16;
                af[mt][0] = As[buf][r + g    ][ks + t];
                af[mt][1] = As[buf][r + g + 8][ks + t];
                af[mt][2] = As[buf][r + g    ][ks + t + 4];
                af[mt][3] = As[buf][r + g + 8][ks + t + 4];
            }
#pragma unroll
            for (int nt = 0; nt < 4; nt++) {
                int c = wn + nt * 8;
                bf[nt][0] = Bs[buf][c + g][ks + t];
                bf[nt][1] = Bs[buf][c + g][ks + t + 4];
            }
#pragma unroll
            for (int mt = 0; mt < 2; mt++)
#pragma unroll
                for (int nt = 0; nt < 4; nt++)
                    mma_tf32(acc[mt][nt], af[mt], bf[nt]);
        }

        if (more) {
            commit(buf ^ 1);
            __syncthreads();
            buf ^= 1;
        }
    }

#pragma unroll
    for (int mt = 0; mt < 2; mt++) {
#pragma unroll
        for (int nt = 0; nt < 4; nt++) {
            int col = j0 + wn + nt * 8 + t * 2;
            if (col >= N) continue;
            float b0 = 0.0f, b1 = 0.0f;
            if (bias) { b0 = bias[col]; b1 = bias[col + 1]; }
#pragma unroll
            for (int half = 0; half < 2; half++) {
                int row = i0 + wm + mt * 16 + g + half * 8;
                if (row >= M) continue;
                float v0 = acc[mt][nt][half * 2 + 0] + b0;
                float v1 = acc[mt][nt][half * 2 + 1] + b1;
                if (act) {
                    v0 = 0.5f * v0 * (1.0f + erff(v0 * 0.70710678118654752f));
                    v1 = 0.5f * v1 * (1.0f + erff(v1 * 0.70710678118654752f));
                }
                *(float2*)&Cb[(long)row * ldcI + col] = make_float2(v0, v1);
            }
        }
    }
}

// ---------------------------------------------------------------------------
__global__ void add_bias2(const float* __restrict__ src,
                          const float* __restrict__ bw,
                          const float* __restrict__ br,
                          float* __restrict__ dw, float* __restrict__ dr, long n)
{
    long idx = (long)blockIdx.x * blockDim.x + threadIdx.x;
    long stride = (long)gridDim.x * blockDim.x;
    for (; idx < n; idx += stride) {
        int c = (int)(idx & (DM - 1));
        float v = src[idx];
        dw[idx] = v + bw[c];
        dr[idx] = v + br[c];
    }
}

// ---------------------------------------------------------------------------
__global__ void softmax_shift(const float* __restrict__ AC,
                              const float* __restrict__ BD,
                              const float* __restrict__ mask,
                              float* __restrict__ P)
{
    const int i = blockIdx.x;
    const int z = blockIdx.y;
    const int b = z >> 4;
    const float* ac = AC + ((long)z * QLEN + i) * KLEN;
    const float* bd = BD + ((long)z * QLEN + i) * RLEN;
    float*       p  = P  + ((long)z * QLEN + i) * KLEN;

    __shared__ float red[256];
    const int tid = threadIdx.x;

    float vals[4];
    float lm = -1e38f;
#pragma unroll
    for (int r = 0; r < 4; r++) {
        int j = tid + r * 256;
        float s = (ac[j] + bd[j - i + KLEN]) * 0.125f
                - 1e30f * mask[((long)i * KLEN + j) * BSZ + b];
        vals[r] = s;
        lm = fmaxf(lm, s);
    }
    red[tid] = lm; __syncthreads();
    for (int s = 128; s > 0; s >>= 1) {
        if (tid < s) red[tid] = fmaxf(red[tid], red[tid + s]);
        __syncthreads();
    }
    float mx = red[0]; __syncthreads();

    float ls = 0.0f;
#pragma unroll
    for (int r = 0; r < 4; r++) {
        vals[r] = __expf(vals[r] - mx);
        ls += vals[r];
    }
    red[tid] = ls; __syncthreads();
    for (int s = 128; s > 0; s >>= 1) {
        if (tid < s) red[tid] += red[tid + s];
        __syncthreads();
    }
    float inv = 1.0f / red[0];
#pragma unroll
    for (int r = 0; r < 4; r++)
        p[tid + r * 256] = vals[r] * inv;
}

// ---------------------------------------------------------------------------
__global__ void ln_res(const float* __restrict__ x, const float* __restrict__ res,
                       const float* __restrict__ sc, const float* __restrict__ bi,
                       float* __restrict__ out)
{
    const long row = blockIdx.x;
    const float* xr = x   + row * DM;
    const float* rr = res + row * DM;
    float*       o  = out + row * DM;
    const int tid = threadIdx.x;

    __shared__ float red[256];

    float v[4];
    float s = 0.0f;
#pragma unroll
    for (int r = 0; r < 4; r++) {
        int c = tid + r * 256;
        v[r] = xr[c] + rr[c];
        s += v[r];
    }
    red[tid] = s; __syncthreads();
    for (int st = 128; st > 0; st >>= 1) {
        if (tid < st) red[tid] += red[tid + st];
        __syncthreads();
    }
    float mean = red[0] * (1.0f / DM); __syncthreads();

    float sq = 0.0f;
#pragma unroll
    for (int r = 0; r < 4; r++) {
        float d = v[r] - mean;
        sq += d * d;
    }
    red[tid] = sq; __syncthreads();
    for (int st = 128; st > 0; st >>= 1) {
        if (tid < st) red[tid] += red[tid + st];
        __syncthreads();
    }
    float rstd = rsqrtf(red[0] * (1.0f / DM) + 1e-8f);
#pragma unroll
    for (int r = 0; r < 4; r++) {
        int c = tid + r * 256;
        o[c] = (v[r] - mean) * rstd * sc[c] + bi[c];
    }
}

// ---------------------------------------------------------------------------
static void launch128(const float* A, const float* B, float* C,
                      int M, int N, int K,
                      long ldaI, long bsA, long ldbK, long ldbJ, long bsB,
                      long ldcI, long bsC,
                      const float* bias, int act, int nb)
{
    gemm_fast<128><<<dim3(N / 128, M / 128, nb), 256>>>(
        A, B, C, M, N, K, ldaI, bsA, ldbK, ldbJ, bsB, ldcI, bsC, bias, act);
}
static void launch64(const float* A, const float* B, float* C,
                     int M, int N, int K,
                     long ldaI, long bsA, long ldbK, long ldbJ, long bsB,
                     long ldcI, long bsC,
                     const float* bias, int act, int nb)
{
    gemm_fast<64><<<dim3(N / 64, M / 128, nb), 256>>>(
        A, B, C, M, N, K, ldaI, bsA, ldbK, ldbJ, bsB, ldcI, bsC, bias, act);
}

extern "C" void kernel_launch(void* const* d_in, const int* in_sizes, int n_in,
                              void* d_out, int out_size)
{
    const float* Xh  = (const float*)d_in[0];
    const float* Xg  = (const float*)d_in[1];
    const float* mh  = (const float*)d_in[2];
    const float* mg  = (const float*)d_in[3];
    const float* R   = (const float*)d_in[4];
    const float* TM  = (const float*)d_in[5];
    const float* qw  = (const float*)d_in[6];
    const float* kw  = (const float*)d_in[7];
    const float* vw  = (const float*)d_in[8];
    const float* rw  = (const float*)d_in[9];
    const float* rrb = (const float*)d_in[10];
    const float* rwb = (const float*)d_in[11];
    const float* lns = (const float*)d_in[12];
    const float* lnb = (const float*)d_in[13];
    const float* w1  = (const float*)d_in[14];
    const float* b1  = (const float*)d_in[15];
    const float* w2  = (const float*)d_in[16];
    const float* b2  = (const float*)d_in[17];
    const float* fls = (const float*)d_in[18];
    const float* flb = (const float*)d_in[19];
    float* out = (float*)d_out;

    float *KH, *VH, *KR, *QT, *QW, *QR, *QG, *AC, *BD, *AV, *AV2,
          *ATTH, *ATTG, *FF1, *FF2;
    cudaGetSymbolAddress((void**)&KH,  g_KH);
    cudaGetSymbolAddress((void**)&VH,  g_VH);
    cudaGetSymbolAddress((void**)&KR,  g_KR);
    cudaGetSymbolAddress((void**)&QT,  g_QT);
    cudaGetSymbolAddress((void**)&QW,  g_QW);
    cudaGetSymbolAddress((void**)&QR,  g_QR);
    cudaGetSymbolAddress((void**)&QG,  g_QG);
    cudaGetSymbolAddress((void**)&AC,  g_AC);
    cudaGetSymbolAddress((void**)&BD,  g_BD);
    cudaGetSymbolAddress((void**)&AV,  g_AV);
    cudaGetSymbolAddress((void**)&AV2, g_AV2);
    cudaGetSymbolAddress((void**)&ATTH, g_ATTH);
    cudaGetSymbolAddress((void**)&ATTG, g_ATTG);
    cudaGetSymbolAddress((void**)&FF1, g_FF1);
    cudaGetSymbolAddress((void**)&FF2, g_FF2);

    const int T = 256;
    const int MH = QLEN * BSZ;     // 4096
    const int MG = NPRED * BSZ;    // 1024

    // ---- shared projections ----
    launch128(Xh, kw, KH, MH, DM, DM, DM, 0, DM, 1, 0, DM, 0, nullptr, 0, 1);
    launch128(Xh, vw, VH, MH, DM, DM, DM, 0, DM, 1, 0, DM, 0, nullptr, 0, 1);
    launch128(R,  rw, KR, RLEN * BSZ, DM, DM, DM, 0, DM, 1, 0, DM, 0, nullptr, 0, 1);

    // ================= h-stream =================
    launch128(Xh, qw, QT, MH, DM, DM, DM, 0, DM, 1, 0, DM, 0, nullptr, 0, 1);
    add_bias2<<<4096, T>>>(QT, rwb, rrb, QW, QR, (long)MH * DM);

    launch128(QW, KH, AC, QLEN, KLEN, DH, 4096, 64, 1, 4096, 64,
              KLEN, (long)QLEN * KLEN, nullptr, 0, NB);
    launch128(QR, KR, BD, QLEN, RLEN, DH, 4096, 64, 1, 4096, 64,
              RLEN, (long)QLEN * RLEN, nullptr, 0, NB);
    softmax_shift<<<dim3(QLEN, NB), T>>>(AC, BD, mh, AC);
    launch64(AC, VH, AV, QLEN, DH, KLEN, KLEN, (long)QLEN * KLEN,
             4096, 1, 64, 4096, 64, nullptr, 0, NB);
    ln_res<<<MH, T>>>(AV, Xh, lns, lnb, ATTH);

    // ================= g-stream =================
    launch128(Xg, qw, QG, MG, DM, DM, DM, 0, DM, 1, 0, DM, 0, nullptr, 0, 1);
    // target-mapping GEMMs: awkward A strides -> generic fallback
    bgemm_tc<<<dim3(DM / BN, QLEN / BM, BSZ), T>>>(TM, QG, QT, QLEN, DM, NPRED,
              4, 4096, 1,   4096, 1, DM,   4096, DM, nullptr, 0);
    add_bias2<<<4096, T>>>(QT, rwb, rrb, QW, QR, (long)MH * DM);

    launch128(QW, KH, AC, QLEN, KLEN, DH, 4096, 64, 1, 4096, 64,
              KLEN, (long)QLEN * KLEN, nullptr, 0, NB);
    launch128(QR, KR, BD, QLEN, RLEN, DH, 4096, 64, 1, 4096, 64,
              RLEN, (long)QLEN * RLEN, nullptr, 0, NB);
    softmax_shift<<<dim3(QLEN, NB), T>>>(AC, BD, mg, AC);
    launch64(AC, VH, AV, QLEN, DH, KLEN, KLEN, (long)QLEN * KLEN,
             4096, 1, 64, 4096, 64, nullptr, 0, NB);
    bgemm_tc<<<dim3(DM / BN, NPRED / BM, BSZ), T>>>(TM, AV, AV2, NPRED, DM, QLEN,
              4096, 4, 1,   4096, 1, DM,   4096, DM, nullptr, 0);
    ln_res<<<MG, T>>>(AV2, Xg, lns, lnb, ATTG);

    // ================= FFN (h) =================
    launch128(ATTH, w1, FF1, MH, DI, DM, DM, 0, DI, 1, 0, DI, 0, b1, 1, 1);
    launch128(FF1, w2, FF2, MH, DM, DI, DI, 0, DM, 1, 0, DM, 0, b2, 0, 1);
    ln_res<<<MH, T>>>(FF2, ATTH, fls, flb, out);

    // ================= FFN (g) =================
    launch128(ATTG, w1, FF1, MG, DI, DM, DM, 0, DI, 1, 0, DI, 0, b1, 1, 1);
    launch128(FF1, w2, FF2, MG, DM, DI, DI, 0, DM, 1, 0, DM, 0, b2, 0, 1);
    ln_res<<<MG, T>>>(FF2, ATTG, fls, flb, out + (long)MH * DM);
}

// round 5
// speedup vs baseline: 3.5632x; 1.0483x over previous
#include <cuda_runtime.h>
#include <cstdint>
#include <math.h>

#define QLEN  1024
#define KLEN  1024
#define RLEN  2048
#define NPRED 256
#define BSZ   4
#define NH    16
#define DH    64
#define DM    1024
#define DI    4096
#define NB    (BSZ*NH)   /* 64 head-batches */

typedef unsigned int u32;

// ---------------------------------------------------------------------------
// Scratch (device globals; allocation in kernel_launch is forbidden)
// ---------------------------------------------------------------------------
__device__ float g_KH [QLEN*BSZ*DM];
__device__ float g_VH [QLEN*BSZ*DM];
__device__ float g_KR [RLEN*BSZ*DM];
__device__ float g_QT [QLEN*BSZ*DM];
__device__ float g_QW [QLEN*BSZ*DM];
__device__ float g_QR [QLEN*BSZ*DM];
__device__ float g_QG [NPRED*BSZ*DM];
__device__ float g_AC [(long)NB*QLEN*KLEN];
__device__ float g_BD [(long)NB*QLEN*RLEN];
__device__ float g_AV [QLEN*BSZ*DM];
__device__ float g_AV2[NPRED*BSZ*DM];
__device__ float g_ATTH[QLEN*BSZ*DM];
__device__ float g_ATTG[NPRED*BSZ*DM];
__device__ float g_FF1[QLEN*BSZ*DI];
__device__ float g_FF2[QLEN*BSZ*DM];

// ---------------------------------------------------------------------------
__device__ __forceinline__ u32 f2tf32(float v)
{
    u32 r;
    asm("cvt.rna.tf32.f32 %0, %1;" : "=r"(r) : "f"(v));
    return r;
}

__device__ __forceinline__ void mma_tf32(float* c, const u32* a, const u32* b)
{
    asm volatile(
        "mma.sync.aligned.m16n8k8.row.col.f32.tf32.tf32.f32 "
        "{%0,%1,%2,%3}, {%4,%5,%6,%7}, {%8,%9}, {%0,%1,%2,%3};\n"
        : "+f"(c[0]), "+f"(c[1]), "+f"(c[2]), "+f"(c[3])
        : "r"(a[0]), "r"(a[1]), "r"(a[2]), "r"(a[3]), "r"(b[0]), "r"(b[1]));
}

__device__ __forceinline__ void ldsm4(u32& r0, u32& r1, u32& r2, u32& r3, u32 addr)
{
    asm volatile(
        "ldmatrix.sync.aligned.m8n8.x4.shared.b16 {%0,%1,%2,%3}, [%4];\n"
        : "=r"(r0), "=r"(r1), "=r"(r2), "=r"(r3) : "r"(addr));
}

// ===========================================================================
// FAST kernel. Requirements (all call sites satisfy):
//   ldaK == 1 (A k-contiguous), M % 128 == 0, K % 16 == 0, N % TBN == 0,
//   B either k-contiguous (ldbK==1) or n-contiguous (ldbJ==1).
// Block tile: 128 x TBN, BK=16, 256 threads. Fragments loaded via LDSM.
// ===========================================================================
#define SK 20   /* smem row stride in u32 */

template<int TBN>
__global__ __launch_bounds__(256, 2) void gemm_fast(
    const float* __restrict__ A, const float* __restrict__ B,
    float* __restrict__ C,
    int M, int N, int K,
    long ldaI, long bsA,
    long ldbK, long ldbJ, long bsB,
    long ldcI, long bsC,
    const float* __restrict__ bias, int act)
{
    constexpr int WARPS_M = (TBN == 128) ? 2 : 4;
    constexpr int WARPS_N = 8 / WARPS_M;
    constexpr int WROWS   = 128 / WARPS_M;   // 64 / 32
    constexpr int WCOLS   = TBN / WARPS_N;   // 32
    constexpr int MT      = WROWS / 16;      // 4 / 2
    constexpr int NT      = WCOLS / 8;       // 4
    constexpr int NBLD    = TBN / 64;        // 2 / 1
    constexpr int ABUF    = 128 * SK * 4;    // bytes per A buffer
    constexpr int BBUF    = TBN * SK * 4;    // bytes per B buffer

    __shared__ u32 As[2][128][SK];
    __shared__ u32 Bs[2][TBN][SK];

    const int z = blockIdx.z;
    const float* Ab = A + (long)z * bsA;
    const float* Bb = B + (long)z * bsB;
    float*       Cb = C + (long)z * bsC;

    const int i0 = blockIdx.y * 128;
    const int j0 = blockIdx.x * TBN;
    const int tid  = threadIdx.x;
    const int warp = tid >> 5;
    const int lane = tid & 31;
    const int g = lane >> 2;
    const int t = lane & 3;
    const int wm = (warp % WARPS_M) * WROWS;
    const int wn = (warp / WARPS_M) * WCOLS;

    // ---- LDSM address precompute (per-lane, loop-invariant) ----
    const u32 sa_base = (u32)__cvta_generic_to_shared(&As[0][0][0]);
    const u32 sb_base = (u32)__cvta_generic_to_shared(&Bs[0][0][0]);
    const int mi = lane >> 3;   // matrix index 0..3
    const int ri = lane & 7;    // row within matrix
    u32 aoff[MT];
#pragma unroll
    for (int mt = 0; mt < MT; mt++)
        aoff[mt] = ((u32)(wm + mt * 16 + (mi & 1) * 8 + ri) * SK + (u32)(mi >> 1) * 4) * 4;
    u32 boff[2];
#pragma unroll
    for (int p = 0; p < 2; p++)
        boff[p] = ((u32)(wn + p * 16 + (mi >> 1) * 8 + ri) * SK + (u32)(mi & 1) * 4) * 4;

    // ---- A staging pointers (vector path, ldaK==1) ----
    const int arow = tid >> 2;            // 0..63
    const int aq4  = (tid & 3) * 4;
    const float* pA0 = Ab + (long)(i0 + arow) * ldaI + aq4;
    const float* pA1 = pA0 + (long)64 * ldaI;

    // ---- B staging pointers ----
    const bool btrans = (ldbJ == 1);      // uniform
    const float* pB[NBLD];
    int bx[NBLD], by[NBLD];               // commit coords
    long bstep;
    if (btrans) {
        bstep = 16 * ldbK;
#pragma unroll
        for (int u = 0; u < NBLD; u++) {
            int idx = tid + 256 * u;
            int nq = idx & (TBN / 4 - 1);
            int kk = idx / (TBN / 4);
            bx[u] = nq * 4; by[u] = kk;
            pB[u] = Bb + (long)kk * ldbK + (long)(j0 + nq * 4);
        }
    } else {
        bstep = 16;
#pragma unroll
        for (int u = 0; u < NBLD; u++) {
            int idx = tid + 256 * u;
            int nr = idx >> 2;
            int q4 = (idx & 3) * 4;
            bx[u] = nr; by[u] = q4;
            pB[u] = Bb + (long)(j0 + nr) * ldbJ + q4;
        }
    }

    float acc[MT][NT][4];
#pragma unroll
    for (int mt = 0; mt < MT; mt++)
#pragma unroll
        for (int nt = 0; nt < NT; nt++)
#pragma unroll
            for (int e = 0; e < 4; e++) acc[mt][nt][e] = 0.0f;

    float4 ra0, ra1, rb[NBLD];

    // prologue: load + commit tile 0
    ra0 = *(const float4*)pA0; pA0 += 16;
    ra1 = *(const float4*)pA1; pA1 += 16;
#pragma unroll
    for (int u = 0; u < NBLD; u++) { rb[u] = *(const float4*)pB[u]; pB[u] += bstep; }

    {
        uint4 w0 = make_uint4(f2tf32(ra0.x), f2tf32(ra0.y), f2tf32(ra0.z), f2tf32(ra0.w));
        *(uint4*)&As[0][arow][aq4] = w0;
        uint4 w1 = make_uint4(f2tf32(ra1.x), f2tf32(ra1.y), f2tf32(ra1.z), f2tf32(ra1.w));
        *(uint4*)&As[0][arow + 64][aq4] = w1;
        if (btrans) {
#pragma unroll
            for (int u = 0; u < NBLD; u++) {
                Bs[0][bx[u] + 0][by[u]] = f2tf32(rb[u].x);
                Bs[0][bx[u] + 1][by[u]] = f2tf32(rb[u].y);
                Bs[0][bx[u] + 2][by[u]] = f2tf32(rb[u].z);
                Bs[0][bx[u] + 3][by[u]] = f2tf32(rb[u].w);
            }
        } else {
#pragma unroll
            for (int u = 0; u < NBLD; u++) {
                uint4 w = make_uint4(f2tf32(rb[u].x), f2tf32(rb[u].y), f2tf32(rb[u].z), f2tf32(rb[u].w));
                *(uint4*)&Bs[0][bx[u]][by[u]] = w;
            }
        }
    }
    __syncthreads();

    const int nk = K >> 4;
    int buf = 0;
    for (int it = 0; it < nk; it++) {
        const bool more = (it + 1) < nk;
        if (more) {
            ra0 = *(const float4*)pA0; pA0 += 16;
            ra1 = *(const float4*)pA1; pA1 += 16;
#pragma unroll
            for (int u = 0; u < NBLD; u++) { rb[u] = *(const float4*)pB[u]; pB[u] += bstep; }
        }

        const u32 abuf = sa_base + (u32)buf * ABUF;
        const u32 bbuf = sb_base + (u32)buf * BBUF;
#pragma unroll
        for (int kk = 0; kk < 2; kk++) {
            const u32 ksb = kk * 32;   // 8 k * 4 bytes
            u32 af[MT][4], bf2[2][4];
#pragma unroll
            for (int mt = 0; mt < MT; mt++)
                ldsm4(af[mt][0], af[mt][1], af[mt][2], af[mt][3], abuf + aoff[mt] + ksb);
#pragma unroll
            for (int p = 0; p < 2; p++)
                ldsm4(bf2[p][0], bf2[p][1], bf2[p][2], bf2[p][3], bbuf + boff[p] + ksb);
#pragma unroll
            for (int mt = 0; mt < MT; mt++)
#pragma unroll
                for (int nt = 0; nt < NT; nt++)
                    mma_tf32(acc[mt][nt], af[mt], &bf2[nt >> 1][(nt & 1) * 2]);
        }

        if (more) {
            int nb2 = buf ^ 1;
            uint4 w0 = make_uint4(f2tf32(ra0.x), f2tf32(ra0.y), f2tf32(ra0.z), f2tf32(ra0.w));
            *(uint4*)&As[nb2][arow][aq4] = w0;
            uint4 w1 = make_uint4(f2tf32(ra1.x), f2tf32(ra1.y), f2tf32(ra1.z), f2tf32(ra1.w));
            *(uint4*)&As[nb2][arow + 64][aq4] = w1;
            if (btrans) {
#pragma unroll
                for (int u = 0; u < NBLD; u++) {
                    Bs[nb2][bx[u] + 0][by[u]] = f2tf32(rb[u].x);
                    Bs[nb2][bx[u] + 1][by[u]] = f2tf32(rb[u].y);
                    Bs[nb2][bx[u] + 2][by[u]] = f2tf32(rb[u].z);
                    Bs[nb2][bx[u] + 3][by[u]] = f2tf32(rb[u].w);
                }
            } else {
#pragma unroll
                for (int u = 0; u < NBLD; u++) {
                    uint4 w = make_uint4(f2tf32(rb[u].x), f2tf32(rb[u].y), f2tf32(rb[u].z), f2tf32(rb[u].w));
                    *(uint4*)&Bs[nb2][bx[u]][by[u]] = w;
                }
            }
            __syncthreads();
            buf = nb2;
        }
    }

    // epilogue
#pragma unroll
    for (int mt = 0; mt < MT; mt++) {
#pragma unroll
        for (int nt = 0; nt < NT; nt++) {
            int col = j0 + wn + nt * 8 + t * 2;
            float b0 = 0.0f, b1 = 0.0f;
            if (bias) { b0 = bias[col]; b1 = bias[col + 1]; }
#pragma unroll
            for (int half = 0; half < 2; half++) {
                int row = i0 + wm + mt * 16 + g + half * 8;
                float v0 = acc[mt][nt][half * 2 + 0] + b0;
                float v1 = acc[mt][nt][half * 2 + 1] + b1;
                if (act) {
                    v0 = 0.5f * v0 * (1.0f + erff(v0 * 0.70710678118654752f));
                    v1 = 0.5f * v1 * (1.0f + erff(v1 * 0.70710678118654752f));
                }
                *(float2*)&Cb[(long)row * ldcI + col] = make_float2(v0, v1);
            }
        }
    }
}

// ===========================================================================
// Generic fallback — used only for the two target-mapping GEMMs.
// ===========================================================================
#define BM 128
#define BN 64
#define BKT 16

__global__ __launch_bounds__(256) void bgemm_tc(
    const float* __restrict__ A, const float* __restrict__ B,
    float* __restrict__ C,
    int M, int N, int K,
    long ldaI, long ldaK, long bsA,
    long ldbK, long ldbJ, long bsB,
    long ldcI, long bsC,
    const float* __restrict__ bias, int act)
{
    __shared__ u32 As[2][BM][BKT + 1];
    __shared__ u32 Bs[2][BN][BKT + 1];

    const int z = blockIdx.z;
    const float* Ab = A + (long)z * bsA;
    const float* Bb = B + (long)z * bsB;
    float*       Cb = C + (long)z * bsC;

    const int i0 = blockIdx.y * BM;
    const int j0 = blockIdx.x * BN;
    const int tid  = threadIdx.x;
    const int warp = tid >> 5;
    const int lane = tid & 31;
    const int g = lane >> 2;
    const int t = lane & 3;
    const int wm = (warp & 3) * 32;
    const int wn = (warp >> 2) * 32;

    const bool ak1 = (ldaK == 1);
    const bool bj1 = (ldbJ == 1);

    float acc[2][4][4];
#pragma unroll
    for (int mt = 0; mt < 2; mt++)
#pragma unroll
        for (int nt = 0; nt < 4; nt++)
#pragma unroll
            for (int e = 0; e < 4; e++) acc[mt][nt][e] = 0.0f;

    float ra[8], rb[4];

    auto stage = [&](int k0) {
#pragma unroll
        for (int u = 0; u < 8; u++) {
            int e = tid + u * 256;
            int i, k;
            if (ak1) { k = e & 15; i = e >> 4; }
            else     { i = e & 127; k = e >> 7; }
            int gi = i0 + i, gk = k0 + k;
            ra[u] = (gi < M && gk < K) ? Ab[(long)gi * ldaI + (long)gk * ldaK] : 0.0f;
        }
#pragma unroll
        for (int u = 0; u < 4; u++) {
            int e = tid + u * 256;
            int n, k;
            if (bj1) { n = e & 63; k = e >> 6; }
            else     { k = e & 15; n = e >> 4; }
            int gn = j0 + n, gk = k0 + k;
            rb[u] = (gn < N && gk < K) ? Bb[(long)gk * ldbK + (long)gn * ldbJ] : 0.0f;
        }
    };
    auto commit = [&](int buf) {
#pragma unroll
        for (int u = 0; u < 8; u++) {
            int e = tid + u * 256;
            int i, k;
            if (ak1) { k = e & 15; i = e >> 4; }
            else     { i = e & 127; k = e >> 7; }
            As[buf][i][k] = f2tf32(ra[u]);
        }
#pragma unroll
        for (int u = 0; u < 4; u++) {
            int e = tid + u * 256;
            int n, k;
            if (bj1) { n = e & 63; k = e >> 6; }
            else     { k = e & 15; n = e >> 4; }
            Bs[buf][n][k] = f2tf32(rb[u]);
        }
    };

    stage(0);
    commit(0);
    __syncthreads();

    int buf = 0;
    for (int k0 = 0; k0 < K; k0 += BKT) {
        const bool more = (k0 + BKT) < K;
        if (more) stage(k0 + BKT);

#pragma unroll
        for (int kk = 0; kk < 2; kk++) {
            const int ks = kk * 8;
            u32 af[2][4], bf[4][2];
#pragma unroll
            for (int mt = 0; mt < 2; mt++) {
                int r = wm + mt * 16;
                af[mt][0] = As[buf][r + g    ][ks + t];
                af[mt][1] = As[buf][r + g + 8][ks + t];
                af[mt][2] = As[buf][r + g    ][ks + t + 4];
                af[mt][3] = As[buf][r + g + 8][ks + t + 4];
            }
#pragma unroll
            for (int nt = 0; nt < 4; nt++) {
                int c = wn + nt * 8;
                bf[nt][0] = Bs[buf][c + g][ks + t];
                bf[nt][1] = Bs[buf][c + g][ks + t + 4];
            }
#pragma unroll
            for (int mt = 0; mt < 2; mt++)
#pragma unroll
                for (int nt = 0; nt < 4; nt++)
                    mma_tf32(acc[mt][nt], af[mt], bf[nt]);
        }

        if (more) {
            commit(buf ^ 1);
            __syncthreads();
            buf ^= 1;
        }
    }

#pragma unroll
    for (int mt = 0; mt < 2; mt++) {
#pragma unroll
        for (int nt = 0; nt < 4; nt++) {
            int col = j0 + wn + nt * 8 + t * 2;
            if (col >= N) continue;
            float b0 = 0.0f, b1 = 0.0f;
            if (bias) { b0 = bias[col]; b1 = bias[col + 1]; }
#pragma unroll
            for (int half = 0; half < 2; half++) {
                int row = i0 + wm + mt * 16 + g + half * 8;
                if (row >= M) continue;
                float v0 = acc[mt][nt][half * 2 + 0] + b0;
                float v1 = acc[mt][nt][half * 2 + 1] + b1;
                if (act) {
                    v0 = 0.5f * v0 * (1.0f + erff(v0 * 0.70710678118654752f));
                    v1 = 0.5f * v1 * (1.0f + erff(v1 * 0.70710678118654752f));
                }
                *(float2*)&Cb[(long)row * ldcI + col] = make_float2(v0, v1);
            }
        }
    }
}

// ---------------------------------------------------------------------------
__global__ void add_bias2(const float* __restrict__ src,
                          const float* __restrict__ bw,
                          const float* __restrict__ br,
                          float* __restrict__ dw, float* __restrict__ dr, long n)
{
    long idx = (long)blockIdx.x * blockDim.x + threadIdx.x;
    long stride = (long)gridDim.x * blockDim.x;
    for (; idx < n; idx += stride) {
        int c = (int)(idx & (DM - 1));
        float v = src[idx];
        dw[idx] = v + bw[c];
        dr[idx] = v + br[c];
    }
}

// ---------------------------------------------------------------------------
__global__ void softmax_shift(const float* __restrict__ AC,
                              const float* __restrict__ BD,
                              const float* __restrict__ mask,
                              float* __restrict__ P)
{
    const int i = blockIdx.x;
    const int z = blockIdx.y;
    const int b = z >> 4;
    const float* ac = AC + ((long)z * QLEN + i) * KLEN;
    const float* bd = BD + ((long)z * QLEN + i) * RLEN;
    float*       p  = P  + ((long)z * QLEN + i) * KLEN;

    __shared__ float red[256];
    const int tid = threadIdx.x;

    float vals[4];
    float lm = -1e38f;
#pragma unroll
    for (int r = 0; r < 4; r++) {
        int j = tid + r * 256;
        float s = (ac[j] + bd[j - i + KLEN]) * 0.125f
                - 1e30f * mask[((long)i * KLEN + j) * BSZ + b];
        vals[r] = s;
        lm = fmaxf(lm, s);
    }
    red[tid] = lm; __syncthreads();
    for (int s = 128; s > 0; s >>= 1) {
        if (tid < s) red[tid] = fmaxf(red[tid], red[tid + s]);
        __syncthreads();
    }
    float mx = red[0]; __syncthreads();

    float ls = 0.0f;
#pragma unroll
    for (int r = 0; r < 4; r++) {
        vals[r] = __expf(vals[r] - mx);
        ls += vals[r];
    }
    red[tid] = ls; __syncthreads();
    for (int s = 128; s > 0; s >>= 1) {
        if (tid < s) red[tid] += red[tid + s];
        __syncthreads();
    }
    float inv = 1.0f / red[0];
#pragma unroll
    for (int r = 0; r < 4; r++)
        p[tid + r * 256] = vals[r] * inv;
}

// ---------------------------------------------------------------------------
__global__ void ln_res(const float* __restrict__ x, const float* __restrict__ res,
                       const float* __restrict__ sc, const float* __restrict__ bi,
                       float* __restrict__ out)
{
    const long row = blockIdx.x;
    const float* xr = x   + row * DM;
    const float* rr = res + row * DM;
    float*       o  = out + row * DM;
    const int tid = threadIdx.x;

    __shared__ float red[256];

    float v[4];
    float s = 0.0f;
#pragma unroll
    for (int r = 0; r < 4; r++) {
        int c = tid + r * 256;
        v[r] = xr[c] + rr[c];
        s += v[r];
    }
    red[tid] = s; __syncthreads();
    for (int st = 128; st > 0; st >>= 1) {
        if (tid < st) red[tid] += red[tid + st];
        __syncthreads();
    }
    float mean = red[0] * (1.0f / DM); __syncthreads();

    float sq = 0.0f;
#pragma unroll
    for (int r = 0; r < 4; r++) {
        float d = v[r] - mean;
        sq += d * d;
    }
    red[tid] = sq; __syncthreads();
    for (int st = 128; st > 0; st >>= 1) {
        if (tid < st) red[tid] += red[tid + st];
        __syncthreads();
    }
    float rstd = rsqrtf(red[0] * (1.0f / DM) + 1e-8f);
#pragma unroll
    for (int r = 0; r < 4; r++) {
        int c = tid + r * 256;
        o[c] = (v[r] - mean) * rstd * sc[c] + bi[c];
    }
}

// ---------------------------------------------------------------------------
static void launch128(const float* A, const float* B, float* C,
                      int M, int N, int K,
                      long ldaI, long bsA, long ldbK, long ldbJ, long bsB,
                      long ldcI, long bsC,
                      const float* bias, int act, int nb)
{
    gemm_fast<128><<<dim3(N / 128, M / 128, nb), 256>>>(
        A, B, C, M, N, K, ldaI, bsA, ldbK, ldbJ, bsB, ldcI, bsC, bias, act);
}
static void launch64(const float* A, const float* B, float* C,
                     int M, int N, int K,
                     long ldaI, long bsA, long ldbK, long ldbJ, long bsB,
                     long ldcI, long bsC,
                     const float* bias, int act, int nb)
{
    gemm_fast<64><<<dim3(N / 64, M / 128, nb), 256>>>(
        A, B, C, M, N, K, ldaI, bsA, ldbK, ldbJ, bsB, ldcI, bsC, bias, act);
}

extern "C" void kernel_launch(void* const* d_in, const int* in_sizes, int n_in,
                              void* d_out, int out_size)
{
    const float* Xh  = (const float*)d_in[0];
    const float* Xg  = (const float*)d_in[1];
    const float* mh  = (const float*)d_in[2];
    const float* mg  = (const float*)d_in[3];
    const float* R   = (const float*)d_in[4];
    const float* TM  = (const float*)d_in[5];
    const float* qw  = (const float*)d_in[6];
    const float* kw  = (const float*)d_in[7];
    const float* vw  = (const float*)d_in[8];
    const float* rw  = (const float*)d_in[9];
    const float* rrb = (const float*)d_in[10];
    const float* rwb = (const float*)d_in[11];
    const float* lns = (const float*)d_in[12];
    const float* lnb = (const float*)d_in[13];
    const float* w1  = (const float*)d_in[14];
    const float* b1  = (const float*)d_in[15];
    const float* w2  = (const float*)d_in[16];
    const float* b2  = (const float*)d_in[17];
    const float* fls = (const float*)d_in[18];
    const float* flb = (const float*)d_in[19];
    float* out = (float*)d_out;

    float *KH, *VH, *KR, *QT, *QW, *QR, *QG, *AC, *BD, *AV, *AV2,
          *ATTH, *ATTG, *FF1, *FF2;
    cudaGetSymbolAddress((void**)&KH,  g_KH);
    cudaGetSymbolAddress((void**)&VH,  g_VH);
    cudaGetSymbolAddress((void**)&KR,  g_KR);
    cudaGetSymbolAddress((void**)&QT,  g_QT);
    cudaGetSymbolAddress((void**)&QW,  g_QW);
    cudaGetSymbolAddress((void**)&QR,  g_QR);
    cudaGetSymbolAddress((void**)&QG,  g_QG);
    cudaGetSymbolAddress((void**)&AC,  g_AC);
    cudaGetSymbolAddress((void**)&BD,  g_BD);
    cudaGetSymbolAddress((void**)&AV,  g_AV);
    cudaGetSymbolAddress((void**)&AV2, g_AV2);
    cudaGetSymbolAddress((void**)&ATTH, g_ATTH);
    cudaGetSymbolAddress((void**)&ATTG, g_ATTG);
    cudaGetSymbolAddress((void**)&FF1, g_FF1);
    cudaGetSymbolAddress((void**)&FF2, g_FF2);

    const int T = 256;
    const int MH = QLEN * BSZ;     // 4096
    const int MG = NPRED * BSZ;    // 1024

    // ---- shared projections ----
    launch128(Xh, kw, KH, MH, DM, DM, DM, 0, DM, 1, 0, DM, 0, nullptr, 0, 1);
    launch128(Xh, vw, VH, MH, DM, DM, DM, 0, DM, 1, 0, DM, 0, nullptr, 0, 1);
    launch128(R,  rw, KR, RLEN * BSZ, DM, DM, DM, 0, DM, 1, 0, DM, 0, nullptr, 0, 1);

    // ================= h-stream =================
    launch128(Xh, qw, QT, MH, DM, DM, DM, 0, DM, 1, 0, DM, 0, nullptr, 0, 1);
    add_bias2<<<4096, T>>>(QT, rwb, rrb, QW, QR, (long)MH * DM);

    launch128(QW, KH, AC, QLEN, KLEN, DH, 4096, 64, 1, 4096, 64,
              KLEN, (long)QLEN * KLEN, nullptr, 0, NB);
    launch128(QR, KR, BD, QLEN, RLEN, DH, 4096, 64, 1, 4096, 64,
              RLEN, (long)QLEN * RLEN, nullptr, 0, NB);
    softmax_shift<<<dim3(QLEN, NB), T>>>(AC, BD, mh, AC);
    launch64(AC, VH, AV, QLEN, DH, KLEN, KLEN, (long)QLEN * KLEN,
             4096, 1, 64, 4096, 64, nullptr, 0, NB);
    ln_res<<<MH, T>>>(AV, Xh, lns, lnb, ATTH);

    // ================= g-stream =================
    launch128(Xg, qw, QG, MG, DM, DM, DM, 0, DM, 1, 0, DM, 0, nullptr, 0, 1);
    bgemm_tc<<<dim3(DM / BN, QLEN / BM, BSZ), T>>>(TM, QG, QT, QLEN, DM, NPRED,
              4, 4096, 1,   4096, 1, DM,   4096, DM, nullptr, 0);
    add_bias2<<<4096, T>>>(QT, rwb, rrb, QW, QR, (long)MH * DM);

    launch128(QW, KH, AC, QLEN, KLEN, DH, 4096, 64, 1, 4096, 64,
              KLEN, (long)QLEN * KLEN, nullptr, 0, NB);
    launch128(QR, KR, BD, QLEN, RLEN, DH, 4096, 64, 1, 4096, 64,
              RLEN, (long)QLEN * RLEN, nullptr, 0, NB);
    softmax_shift<<<dim3(QLEN, NB), T>>>(AC, BD, mg, AC);
    launch64(AC, VH, AV, QLEN, DH, KLEN, KLEN, (long)QLEN * KLEN,
             4096, 1, 64, 4096, 64, nullptr, 0, NB);
    bgemm_tc<<<dim3(DM / BN, NPRED / BM, BSZ), T>>>(TM, AV, AV2, NPRED, DM, QLEN,
              4096, 4, 1,   4096, 1, DM,   4096, DM, nullptr, 0);
    ln_res<<<MG, T>>>(AV2, Xg, lns, lnb, ATTG);

    // ================= FFN (h) =================
    launch128(ATTH, w1, FF1, MH, DI, DM, DM, 0, DI, 1, 0, DI, 0, b1, 1, 1);
    launch128(FF1, w2, FF2, MH, DM, DI, DI, 0, DM, 1, 0, DM, 0, b2, 0, 1);
    ln_res<<<MH, T>>>(FF2, ATTH, fls, flb, out);

    // ================= FFN (g) =================
    launch128(ATTG, w1, FF1, MG, DI, DM, DM, 0, DI, 1, 0, DI, 0, b1, 1, 1);
    launch128(FF1, w2, FF2, MG, DM, DI, DI, 0, DM, 1, 0, DM, 0, b2, 0, 1);
    ln_res<<<MG, T>>>(FF2, ATTG, fls, flb, out + (long)MH * DM);
}

// round 7
// speedup vs baseline: 5.4444x; 1.5279x over previous
#include <cuda_runtime.h>
#include <cstdint>
#include <math.h>

#define QLEN  1024
#define KLEN  1024
#define RLEN  2048
#define NPRED 256
#define BSZ   4
#define NH    16
#define DH    64
#define DM    1024
#define DI    4096
#define NB    (BSZ*NH)   /* 64 head-batches */

typedef unsigned int u32;

// ---------------------------------------------------------------------------
// Scratch (device globals; allocation in kernel_launch is forbidden)
// ---------------------------------------------------------------------------
__device__ float g_KH [QLEN*BSZ*DM];
__device__ float g_VH [QLEN*BSZ*DM];
__device__ float g_KR [RLEN*BSZ*DM];
__device__ float g_QT [QLEN*BSZ*DM];
__device__ float g_QW [QLEN*BSZ*DM];
__device__ float g_QR [QLEN*BSZ*DM];
__device__ float g_QG [NPRED*BSZ*DM];
__device__ float g_AC [(long)NB*QLEN*KLEN];
__device__ float g_BD [(long)NB*QLEN*RLEN];
__device__ float g_AV [QLEN*BSZ*DM];
__device__ float g_AV2[NPRED*BSZ*DM];
__device__ float g_ATTH[QLEN*BSZ*DM];
__device__ float g_ATTG[NPRED*BSZ*DM];
__device__ float g_FF1[QLEN*BSZ*DI];
__device__ float g_FF2[QLEN*BSZ*DM];

// ---------------------------------------------------------------------------
__device__ __forceinline__ u32 f2tf32(float v)
{
    u32 r;
    asm("cvt.rna.tf32.f32 %0, %1;" : "=r"(r) : "f"(v));
    return r;
}
__device__ __forceinline__ u32 cvtu(u32 raw)
{
    u32 r;
    asm("cvt.rna.tf32.f32 %0, %1;" : "=r"(r) : "f"(__uint_as_float(raw)));
    return r;
}

__device__ __forceinline__ void mma_tf32(float* c, const u32* a, const u32* b)
{
    asm volatile(
        "mma.sync.aligned.m16n8k8.row.col.f32.tf32.tf32.f32 "
        "{%0,%1,%2,%3}, {%4,%5,%6,%7}, {%8,%9}, {%0,%1,%2,%3};\n"
        : "+f"(c[0]), "+f"(c[1]), "+f"(c[2]), "+f"(c[3])
        : "r"(a[0]), "r"(a[1]), "r"(a[2]), "r"(a[3]), "r"(b[0]), "r"(b[1]));
}

__device__ __forceinline__ void ldsm4(u32& r0, u32& r1, u32& r2, u32& r3, u32 addr)
{
    asm volatile(
        "ldmatrix.sync.aligned.m8n8.x4.shared.b16 {%0,%1,%2,%3}, [%4];\n"
        : "=r"(r0), "=r"(r1), "=r"(r2), "=r"(r3) : "r"(addr));
}

__device__ __forceinline__ void cpa16(u32 saddr, const void* gaddr)
{
    asm volatile("cp.async.cg.shared.global [%0], [%1], 16;\n"
                 :: "r"(saddr), "l"(gaddr));
}
__device__ __forceinline__ void cpa_commit() { asm volatile("cp.async.commit_group;\n"); }
__device__ __forceinline__ void cpa_wait1()  { asm volatile("cp.async.wait_group 1;\n"); }

// ===========================================================================
// FAST kernel. Requirements (all call sites satisfy):
//   A k-contiguous, M % 128 == 0, K % 16 == 0, N % TBN == 0.
//   BTR=1: B n-contiguous (row stride ldb along k).  BTR=0: B k-contiguous
//   (stride ldb along n).
// 3-stage cp.async pipeline, 128 x TBN tile, BK=16, 256 threads.
// ===========================================================================
#define SK 20   /* A / B(ldsm) smem row stride in u32 */

template<int TBN, int BTR>
__global__ __launch_bounds__(256, 2) void gemm_fast(
    const float* __restrict__ A, const float* __restrict__ B,
    float* __restrict__ C, int K,
    long ldaI, long bsA,
    long ldb,  long bsB,
    long ldcI, long bsC,
    const float* __restrict__ bias, int act, int diagskip,
    float* __restrict__ C2, const float* __restrict__ bias2)
{
    constexpr int WARPS_M = (TBN == 128) ? 2 : 4;
    constexpr int MT      = (128 / WARPS_M) / 16;     // 4 / 2
    constexpr int NT      = 4;                        // warp covers 32 cols
    constexpr int NCHB    = TBN / 64;                 // B chunks per thread
    constexpr int BSTR    = BTR ? (TBN + 8) : SK;     // B smem row stride (u32)
    constexpr int ABUF    = 128 * SK * 4;             // bytes per A stage
    constexpr int BBUF    = (BTR ? 16 * BSTR : TBN * SK) * 4;

    extern __shared__ __align__(16) u32 dyn[];
    u32* Asp = dyn;                    // [3][128][SK]
    u32* Bsp = dyn + 3 * 128 * SK;     // [3][...]

    const int i0 = blockIdx.y * 128;
    const int j0 = blockIdx.x * TBN;
    if (diagskip && (i0 + j0 < 770 || i0 + j0 > 2047)) return;

    const int z = blockIdx.z;
    const float* Ab = A + (long)z * bsA;
    const float* Bb = B + (long)z * bsB;
    float*       Cb = C + (long)z * bsC;

    const int tid  = threadIdx.x;
    const int warp = tid >> 5;
    const int lane = tid & 31;
    const int g = lane >> 2;
    const int t = lane & 3;
    const int wm = (warp % WARPS_M) * (128 / WARPS_M);
    const int wn = (warp / WARPS_M) * 32;

    const u32 sa_base = (u32)__cvta_generic_to_shared(Asp);
    const u32 sb_base = (u32)__cvta_generic_to_shared(Bsp);

    // ---- fragment addresses (loop-invariant) ----
    const int mi = lane >> 3;
    const int ri = lane & 7;
    u32 aoff[MT];
#pragma unroll
    for (int mt = 0; mt < MT; mt++)
        aoff[mt] = ((u32)(wm + mt * 16 + (mi & 1) * 8 + ri) * SK + (u32)(mi >> 1) * 4) * 4;
    u32 boff[2];
#pragma unroll
    for (int p = 0; p < 2; p++)
        boff[p] = ((u32)(wn + p * 16 + (mi >> 1) * 8 + ri) * SK + (u32)(mi & 1) * 4) * 4;

    // ---- staging descriptors ----
    const int arow = tid >> 2;
    const int aq4  = (tid & 3) * 4;
    u32 sAo[2];
    const float* gA[2];
    sAo[0] = ((u32)arow * SK + aq4) * 4;
    sAo[1] = ((u32)(arow + 64) * SK + aq4) * 4;
    gA[0] = Ab + (long)(i0 + arow) * ldaI + aq4;
    gA[1] = Ab + (long)(i0 + arow + 64) * ldaI + aq4;

    u32 sBo[NCHB];
    const float* gB[NCHB];
    long bstep;
    if (BTR) {
        bstep = 16 * ldb;
#pragma unroll
        for (int u = 0; u < NCHB; u++) {
            int idx = tid + 256 * u;
            int k  = idx / (TBN / 4);
            int n4 = (idx % (TBN / 4)) * 4;
            sBo[u] = ((u32)k * BSTR + n4) * 4;
            gB[u]  = Bb + (long)k * ldb + (j0 + n4);
        }
    } else {
        bstep = 16;
#pragma unroll
        for (int u = 0; u < NCHB; u++) {
            int idx = tid + 256 * u;
            int n  = idx >> 2;
            int q4 = (idx & 3) * 4;
            sBo[u] = ((u32)n * SK + q4) * 4;
            gB[u]  = Bb + (long)(j0 + n) * ldb + q4;
        }
    }

    const int nk = K >> 4;

    auto issue = [&](int stage, int it) {
        u32 ab = sa_base + (u32)stage * ABUF;
        u32 bb = sb_base + (u32)stage * BBUF;
        long ka = (long)it * 16;
        long kb = (long)it * bstep;
        cpa16(ab + sAo[0], gA[0] + ka);
        cpa16(ab + sAo[1], gA[1] + ka);
#pragma unroll
        for (int u = 0; u < NCHB; u++)
            cpa16(bb + sBo[u], gB[u] + kb);
    };

    float acc[MT][NT][4];
#pragma unroll
    for (int mt = 0; mt < MT; mt++)
#pragma unroll
        for (int nt = 0; nt < NT; nt++)
#pragma unroll
            for (int e = 0; e < 4; e++) acc[mt][nt][e] = 0.0f;

    // prologue
    issue(0, 0); cpa_commit();
    if (nk > 1) issue(1, 1);
    cpa_commit();

    int buf = 0;
    for (int it = 0; it < nk; it++) {
        cpa_wait1();
        __syncthreads();

        const u32 ab = sa_base + (u32)buf * ABUF;
        const u32 bb = sb_base + (u32)buf * BBUF;
        const u32* Brow = Bsp + buf * (BBUF / 4);

#pragma unroll
        for (int kk = 0; kk < 2; kk++) {
            const u32 ksb = kk * 32;
            const int ks  = kk * 8;
            u32 af[MT][4], bf2[2][4];
#pragma unroll
            for (int mt = 0; mt < MT; mt++) {
                ldsm4(af[mt][0], af[mt][1], af[mt][2], af[mt][3], ab + aoff[mt] + ksb);
                af[mt][0] = cvtu(af[mt][0]); af[mt][1] = cvtu(af[mt][1]);
                af[mt][2] = cvtu(af[mt][2]); af[mt][3] = cvtu(af[mt][3]);
            }
            if (BTR) {
#pragma unroll
                for (int p = 0; p < 2; p++) {
                    int c = wn + p * 16;
                    bf2[p][0] = cvtu(Brow[(ks + t) * BSTR + c + g]);
                    bf2[p][1] = cvtu(Brow[(ks + t + 4) * BSTR + c + g]);
                    bf2[p][2] = cvtu(Brow[(ks + t) * BSTR + c + 8 + g]);
                    bf2[p][3] = cvtu(Brow[(ks + t + 4) * BSTR + c + 8 + g]);
                }
            } else {
#pragma unroll
                for (int p = 0; p < 2; p++) {
                    ldsm4(bf2[p][0], bf2[p][1], bf2[p][2], bf2[p][3], bb + boff[p] + ksb);
                    bf2[p][0] = cvtu(bf2[p][0]); bf2[p][1] = cvtu(bf2[p][1]);
                    bf2[p][2] = cvtu(bf2[p][2]); bf2[p][3] = cvtu(bf2[p][3]);
                }
            }
#pragma unroll
            for (int mt = 0; mt < MT; mt++)
#pragma unroll
                for (int nt = 0; nt < NT; nt++)
                    mma_tf32(acc[mt][nt], af[mt], &bf2[nt >> 1][(nt & 1) * 2]);
        }

        int ns = it + 2;
        if (ns < nk) issue(ns >= 3 ? ns - 3 * (ns / 3) : ns, ns);  // stage = ns % 3
        cpa_commit();
        buf = (buf == 2) ? 0 : buf + 1;
    }

    // epilogue
#pragma unroll
    for (int mt = 0; mt < MT; mt++) {
#pragma unroll
        for (int nt = 0; nt < NT; nt++) {
            int col = j0 + wn + nt * 8 + t * 2;
            float b0 = 0.0f, b1 = 0.0f;
            if (bias) { b0 = bias[col]; b1 = bias[col + 1]; }
            float c0 = 0.0f, c1 = 0.0f;
            if (C2) { c0 = bias2[col]; c1 = bias2[col + 1]; }
#pragma unroll
            for (int half = 0; half < 2; half++) {
                int row = i0 + wm + mt * 16 + g + half * 8;
                float a0 = acc[mt][nt][half * 2 + 0];
                float a1 = acc[mt][nt][half * 2 + 1];
                float v0 = a0 + b0, v1 = a1 + b1;
                if (act) {
                    v0 = 0.5f * v0 * (1.0f + erff(v0 * 0.70710678118654752f));
                    v1 = 0.5f * v1 * (1.0f + erff(v1 * 0.70710678118654752f));
                }
                *(float2*)&Cb[(long)row * ldcI + col] = make_float2(v0, v1);
                if (C2)
                    *(float2*)&C2[(long)row * ldcI + col] = make_float2(a0 + c0, a1 + c1);
            }
        }
    }
}

// ===========================================================================
// Generic fallback — used only for the two target-mapping GEMMs.
// ===========================================================================
#define BM 128
#define BN 64
#define BKT 16

__global__ __launch_bounds__(256) void bgemm_tc(
    const float* __restrict__ A, const float* __restrict__ B,
    float* __restrict__ C,
    int M, int N, int K,
    long ldaI, long ldaK, long bsA,
    long ldbK, long ldbJ, long bsB,
    long ldcI, long bsC)
{
    __shared__ u32 As[2][BM][BKT + 1];
    __shared__ u32 Bs[2][BN][BKT + 1];

    const int z = blockIdx.z;
    const float* Ab = A + (long)z * bsA;
    const float* Bb = B + (long)z * bsB;
    float*       Cb = C + (long)z * bsC;

    const int i0 = blockIdx.y * BM;
    const int j0 = blockIdx.x * BN;
    const int tid  = threadIdx.x;
    const int warp = tid >> 5;
    const int lane = tid & 31;
    const int g = lane >> 2;
    const int t = lane & 3;
    const int wm = (warp & 3) * 32;
    const int wn = (warp >> 2) * 32;

    const bool ak1 = (ldaK == 1);
    const bool bj1 = (ldbJ == 1);

    float acc[2][4][4];
#pragma unroll
    for (int mt = 0; mt < 2; mt++)
#pragma unroll
        for (int nt = 0; nt < 4; nt++)
#pragma unroll
            for (int e = 0; e < 4; e++) acc[mt][nt][e] = 0.0f;

    float ra[8], rb[4];

    auto stage = [&](int k0) {
#pragma unroll
        for (int u = 0; u < 8; u++) {
            int e = tid + u * 256;
            int i, k;
            if (ak1) { k = e & 15; i = e >> 4; }
            else     { i = e & 127; k = e >> 7; }
            int gi = i0 + i, gk = k0 + k;
            ra[u] = (gi < M && gk < K) ? Ab[(long)gi * ldaI + (long)gk * ldaK] : 0.0f;
        }
#pragma unroll
        for (int u = 0; u < 4; u++) {
            int e = tid + u * 256;
            int n, k;
            if (bj1) { n = e & 63; k = e >> 6; }
            else     { k = e & 15; n = e >> 4; }
            int gn = j0 + n, gk = k0 + k;
            rb[u] = (gn < N && gk < K) ? Bb[(long)gk * ldbK + (long)gn * ldbJ] : 0.0f;
        }
    };
    auto commit = [&](int buf) {
#pragma unroll
        for (int u = 0; u < 8; u++) {
            int e = tid + u * 256;
            int i, k;
            if (ak1) { k = e & 15; i = e >> 4; }
            else     { i = e & 127; k = e >> 7; }
            As[buf][i][k] = f2tf32(ra[u]);
        }
#pragma unroll
        for (int u = 0; u < 4; u++) {
            int e = tid + u * 256;
            int n, k;
            if (bj1) { n = e & 63; k = e >> 6; }
            else     { k = e & 15; n = e >> 4; }
            Bs[buf][n][k] = f2tf32(rb[u]);
        }
    };

    stage(0);
    commit(0);
    __syncthreads();

    int buf = 0;
    for (int k0 = 0; k0 < K; k0 += BKT) {
        const bool more = (k0 + BKT) < K;
        if (more) stage(k0 + BKT);

#pragma unroll
        for (int kk = 0; kk < 2; kk++) {
            const int ks = kk * 8;
            u32 af[2][4], bf[4][2];
#pragma unroll
            for (int mt = 0; mt < 2; mt++) {
                int r = wm + mt * 16;
                af[mt][0] = As[buf][r + g    ][ks + t];
                af[mt][1] = As[buf][r + g + 8][ks + t];
                af[mt][2] = As[buf][r + g    ][ks + t + 4];
                af[mt][3] = As[buf][r + g + 8][ks + t + 4];
            }
#pragma unroll
            for (int nt = 0; nt < 4; nt++) {
                int c = wn + nt * 8;
                bf[nt][0] = Bs[buf][c + g][ks + t];
                bf[nt][1] = Bs[buf][c + g][ks + t + 4];
            }
#pragma unroll
            for (int mt = 0; mt < 2; mt++)
#pragma unroll
                for (int nt = 0; nt < 4; nt++)
                    mma_tf32(acc[mt][nt], af[mt], bf[nt]);
        }

        if (more) {
            commit(buf ^ 1);
            __syncthreads();
            buf ^= 1;
        }
    }

#pragma unroll
    for (int mt = 0; mt < 2; mt++) {
#pragma unroll
        for (int nt = 0; nt < 4; nt++) {
            int col = j0 + wn + nt * 8 + t * 2;
            if (col >= N) continue;
#pragma unroll
            for (int half = 0; half < 2; half++) {
                int row = i0 + wm + mt * 16 + g + half * 8;
                if (row >= M) continue;
                *(float2*)&Cb[(long)row * ldcI + col] =
                    make_float2(acc[mt][nt][half * 2 + 0], acc[mt][nt][half * 2 + 1]);
            }
        }
    }
}

// ---------------------------------------------------------------------------
__global__ void add_bias2(const float* __restrict__ src,
                          const float* __restrict__ bw,
                          const float* __restrict__ br,
                          float* __restrict__ dw, float* __restrict__ dr, long n)
{
    long idx = (long)blockIdx.x * blockDim.x + threadIdx.x;
    long stride = (long)gridDim.x * blockDim.x;
    for (; idx < n; idx += stride) {
        int c = (int)(idx & (DM - 1));
        float v = src[idx];
        dw[idx] = v + bw[c];
        dr[idx] = v + br[c];
    }
}

// ---------------------------------------------------------------------------
__global__ void softmax_shift(const float* __restrict__ AC,
                              const float* __restrict__ BD,
                              const float* __restrict__ mask,
                              float* __restrict__ P)
{
    const int i = blockIdx.x;
    const int z = blockIdx.y;
    const int b = z >> 4;
    const float* ac = AC + ((long)z * QLEN + i) * KLEN;
    const float* bd = BD + ((long)z * QLEN + i) * RLEN;
    float*       p  = P  + ((long)z * QLEN + i) * KLEN;

    __shared__ float red[256];
    const int tid = threadIdx.x;

    float vals[4];
    float lm = -1e38f;
#pragma unroll
    for (int r = 0; r < 4; r++) {
        int j = tid + r * 256;
        float s = (ac[j] + bd[j - i + KLEN]) * 0.125f
                - 1e30f * mask[((long)i * KLEN + j) * BSZ + b];
        vals[r] = s;
        lm = fmaxf(lm, s);
    }
    red[tid] = lm; __syncthreads();
    for (int s = 128; s > 0; s >>= 1) {
        if (tid < s) red[tid] = fmaxf(red[tid], red[tid + s]);
        __syncthreads();
    }
    float mx = red[0]; __syncthreads();

    float ls = 0.0f;
#pragma unroll
    for (int r = 0; r < 4; r++) {
        vals[r] = __expf(vals[r] - mx);
        ls += vals[r];
    }
    red[tid] = ls; __syncthreads();
    for (int s = 128; s > 0; s >>= 1) {
        if (tid < s) red[tid] += red[tid + s];
        __syncthreads();
    }
    float inv = 1.0f / red[0];
#pragma unroll
    for (int r = 0; r < 4; r++)
        p[tid + r * 256] = vals[r] * inv;
}

// ---------------------------------------------------------------------------
__global__ void ln_res(const float* __restrict__ x, const float* __restrict__ res,
                       const float* __restrict__ sc, const float* __restrict__ bi,
                       float* __restrict__ out)
{
    const long row = blockIdx.x;
    const float* xr = x   + row * DM;
    const float* rr = res + row * DM;
    float*       o  = out + row * DM;
    const int tid = threadIdx.x;

    __shared__ float red[256];

    float v[4];
    float s = 0.0f;
#pragma unroll
    for (int r = 0; r < 4; r++) {
        int c = tid + r * 256;
        v[r] = xr[c] + rr[c];
        s += v[r];
    }
    red[tid] = s; __syncthreads();
    for (int st = 128; st > 0; st >>= 1) {
        if (tid < st) red[tid] += red[tid + st];
        __syncthreads();
    }
    float mean = red[0] * (1.0f / DM); __syncthreads();

    float sq = 0.0f;
#pragma unroll
    for (int r = 0; r < 4; r++) {
        float d = v[r] - mean;
        sq += d * d;
    }
    red[tid] = sq; __syncthreads();
    for (int st = 128; st > 0; st >>= 1) {
        if (tid < st) red[tid] += red[tid + st];
        __syncthreads();
    }
    float rstd = rsqrtf(red[0] * (1.0f / DM) + 1e-8f);
#pragma unroll
    for (int r = 0; r < 4; r++) {
        int c = tid + r * 256;
        o[c] = (v[r] - mean) * rstd * sc[c] + bi[c];
    }
}

// ---------------------------------------------------------------------------
template<int TBN, int BTR>
static void launchG(const float* A, const float* B, float* C,
                    int M, int N, int K,
                    long ldaI, long bsA, long ldb, long bsB,
                    long ldcI, long bsC,
                    const float* bias, int act, int nb, int diagskip = 0,
                    float* C2 = nullptr, const float* bias2 = nullptr)
{
    constexpr int BSTR = BTR ? (TBN + 8) : SK;
    constexpr int SMEM = (3 * 128 * SK + 3 * (BTR ? 16 * BSTR : TBN * SK)) * 4;
    cudaFuncSetAttribute(gemm_fast<TBN, BTR>,
                         cudaFuncAttributeMaxDynamicSharedMemorySize, SMEM);
    gemm_fast<TBN, BTR><<<dim3(N / TBN, M / 128, nb), 256, SMEM>>>(
        A, B, C, K, ldaI, bsA, ldb, bsB, ldcI, bsC, bias, act, diagskip, C2, bias2);
}

extern "C" void kernel_launch(void* const* d_in, const int* in_sizes, int n_in,
                              void* d_out, int out_size)
{
    const float* Xh  = (const float*)d_in[0];
    const float* Xg  = (const float*)d_in[1];
    const float* mh  = (const float*)d_in[2];
    const float* mg  = (const float*)d_in[3];
    const float* R   = (const float*)d_in[4];
    const float* TM  = (const float*)d_in[5];
    const float* qw  = (const float*)d_in[6];
    const float* kw  = (const float*)d_in[7];
    const float* vw  = (const float*)d_in[8];
    const float* rw  = (const float*)d_in[9];
    const float* rrb = (const float*)d_in[10];
    const float* rwb = (const float*)d_in[11];
    const float* lns = (const float*)d_in[12];
    const float* lnb = (const float*)d_in[13];
    const float* w1  = (const float*)d_in[14];
    const float* b1  = (const float*)d_in[15];
    const float* w2  = (const float*)d_in[16];
    const float* b2  = (const float*)d_in[17];
    const float* fls = (const float*)d_in[18];
    const float* flb = (const float*)d_in[19];
    float* out = (float*)d_out;

    float *KH, *VH, *KR, *QT, *QW, *QR, *QG, *AC, *BD, *AV, *AV2,
          *ATTH, *ATTG, *FF1, *FF2;
    cudaGetSymbolAddress((void**)&KH,  g_KH);
    cudaGetSymbolAddress((void**)&VH,  g_VH);
    cudaGetSymbolAddress((void**)&KR,  g_KR);
    cudaGetSymbolAddress((void**)&QT,  g_QT);
    cudaGetSymbolAddress((void**)&QW,  g_QW);
    cudaGetSymbolAddress((void**)&QR,  g_QR);
    cudaGetSymbolAddress((void**)&QG,  g_QG);
    cudaGetSymbolAddress((void**)&AC,  g_AC);
    cudaGetSymbolAddress((void**)&BD,  g_BD);
    cudaGetSymbolAddress((void**)&AV,  g_AV);
    cudaGetSymbolAddress((void**)&AV2, g_AV2);
    cudaGetSymbolAddress((void**)&ATTH, g_ATTH);
    cudaGetSymbolAddress((void**)&ATTG, g_ATTG);
    cudaGetSymbolAddress((void**)&FF1, g_FF1);
    cudaGetSymbolAddress((void**)&FF2, g_FF2);

    const int T = 256;
    const int MH = QLEN * BSZ;     // 4096
    const int MG = NPRED * BSZ;    // 1024

    // ---- shared projections (B n-contiguous weights) ----
    launchG<128,1>(Xh, kw, KH, MH, DM, DM, DM, 0, DM, 0, DM, 0, nullptr, 0, 1);
    launchG<128,1>(Xh, vw, VH, MH, DM, DM, DM, 0, DM, 0, DM, 0, nullptr, 0, 1);
    launchG<128,1>(R,  rw, KR, RLEN * BSZ, DM, DM, DM, 0, DM, 0, DM, 0, nullptr, 0, 1);

    // ================= h-stream =================
    // fused Q projection: QW = Xh@qw + r_w_bias, QR = Xh@qw + r_r_bias
    launchG<128,1>(Xh, qw, QW, MH, DM, DM, DM, 0, DM, 0, DM, 0, rwb, 0, 1, 0, QR, rrb);

    launchG<128,0>(QW, KH, AC, QLEN, KLEN, DH, 4096, 64, 4096, 64,
                   KLEN, (long)QLEN * KLEN, nullptr, 0, NB);
    launchG<128,0>(QR, KR, BD, QLEN, RLEN, DH, 4096, 64, 4096, 64,
                   RLEN, (long)QLEN * RLEN, nullptr, 0, NB, 1);
    softmax_shift<<<dim3(QLEN, NB), T>>>(AC, BD, mh, AC);
    launchG<64,1>(AC, VH, AV, QLEN, DH, KLEN, KLEN, (long)QLEN * KLEN,
                  4096, 64, 4096, 64, nullptr, 0, NB);
    ln_res<<<MH, T>>>(AV, Xh, lns, lnb, ATTH);

    // ================= g-stream =================
    launchG<128,1>(Xg, qw, QG, MG, DM, DM, DM, 0, DM, 0, DM, 0, nullptr, 0, 1);
    bgemm_tc<<<dim3(DM / BN, QLEN / BM, BSZ), T>>>(TM, QG, QT, QLEN, DM, NPRED,
              4, 4096, 1,   4096, 1, DM,   4096, DM);
    add_bias2<<<4096, T>>>(QT, rwb, rrb, QW, QR, (long)MH * DM);

    launchG<128,0>(QW, KH, AC, QLEN, KLEN, DH, 4096, 64, 4096, 64,
                   KLEN, (long)QLEN * KLEN, nullptr, 0, NB);
    launchG<128,0>(QR, KR, BD, QLEN, RLEN, DH, 4096, 64, 4096, 64,
                   RLEN, (long)QLEN * RLEN, nullptr, 0, NB, 1);
    softmax_shift<<<dim3(QLEN, NB), T>>>(AC, BD, mg, AC);
    launchG<64,1>(AC, VH, AV, QLEN, DH, KLEN, KLEN, (long)QLEN * KLEN,
                  4096, 64, 4096, 64, nullptr, 0, NB);
    bgemm_tc<<<dim3(DM / BN, NPRED / BM, BSZ), T>>>(TM, AV, AV2, NPRED, DM, QLEN,
              4096, 4, 1,   4096, 1, DM,   4096, DM);
    ln_res<<<MG, T>>>(AV2, Xg, lns, lnb, ATTG);

    // ================= FFN (h) =================
    launchG<128,1>(ATTH, w1, FF1, MH, DI, DM, DM, 0, DI, 0, DI, 0, b1, 1, 1);
    launchG<128,1>(FF1, w2, FF2, MH, DM, DI, DI, 0, DM, 0, DM, 0, b2, 0, 1);
    ln_res<<<MH, T>>>(FF2, ATTH, fls, flb, out);

    // ================= FFN (g) =================
    launchG<128,1>(ATTG, w1, FF1, MG, DI, DM, DM, 0, DI, 0, DI, 0, b1, 1, 1);
    launchG<128,1>(FF1, w2, FF2, MG, DM, DI, DI, 0, DM, 0, DM, 0, b2, 0, 1);
    ln_res<<<MG, T>>>(FF2, ATTG, fls, flb, out + (long)MH * DM);
}

// round 8
// speedup vs baseline: 5.6295x; 1.0340x over previous
#include <cuda_runtime.h>
#include <cstdint>
#include <math.h>

#define QLEN  1024
#define KLEN  1024
#define RLEN  2048
#define NPRED 256
#define BSZ   4
#define NH    16
#define DH    64
#define DM    1024
#define DI    4096
#define NB    (BSZ*NH)   /* 64 head-batches */

typedef unsigned int u32;

// ---------------------------------------------------------------------------
// Scratch (device globals; allocation in kernel_launch is forbidden)
// ---------------------------------------------------------------------------
__device__ float g_KH [QLEN*BSZ*DM];
__device__ float g_VH [QLEN*BSZ*DM];
__device__ float g_KR [RLEN*BSZ*DM];
__device__ float g_QT [QLEN*BSZ*DM];
__device__ float g_QW [QLEN*BSZ*DM];
__device__ float g_QR [QLEN*BSZ*DM];
__device__ float g_QG [NPRED*BSZ*DM];
__device__ float g_AC [(long)NB*QLEN*KLEN];
__device__ float g_BD [(long)NB*QLEN*RLEN];
__device__ float g_AV [QLEN*BSZ*DM];
__device__ float g_AV2[NPRED*BSZ*DM];
__device__ float g_ATTH[QLEN*BSZ*DM];
__device__ float g_ATTG[NPRED*BSZ*DM];
__device__ float g_FF1[QLEN*BSZ*DI];
__device__ float g_FF2[QLEN*BSZ*DM];

// ---------------------------------------------------------------------------
__device__ __forceinline__ u32 f2tf32(float v)
{
    u32 r;
    asm("cvt.rna.tf32.f32 %0, %1;" : "=r"(r) : "f"(v));
    return r;
}
__device__ __forceinline__ u32 cvtu(u32 raw)
{
    u32 r;
    asm("cvt.rna.tf32.f32 %0, %1;" : "=r"(r) : "f"(__uint_as_float(raw)));
    return r;
}
__device__ __forceinline__ float tf32r(float v)
{
    return __uint_as_float(f2tf32(v));
}

__device__ __forceinline__ void mma_tf32(float* c, const u32* a, const u32* b)
{
    asm volatile(
        "mma.sync.aligned.m16n8k8.row.col.f32.tf32.tf32.f32 "
        "{%0,%1,%2,%3}, {%4,%5,%6,%7}, {%8,%9}, {%0,%1,%2,%3};\n"
        : "+f"(c[0]), "+f"(c[1]), "+f"(c[2]), "+f"(c[3])
        : "r"(a[0]), "r"(a[1]), "r"(a[2]), "r"(a[3]), "r"(b[0]), "r"(b[1]));
}

__device__ __forceinline__ void ldsm4(u32& r0, u32& r1, u32& r2, u32& r3, u32 addr)
{
    asm volatile(
        "ldmatrix.sync.aligned.m8n8.x4.shared.b16 {%0,%1,%2,%3}, [%4];\n"
        : "=r"(r0), "=r"(r1), "=r"(r2), "=r"(r3) : "r"(addr));
}

__device__ __forceinline__ void cpa16(u32 saddr, const void* gaddr)
{
    asm volatile("cp.async.cg.shared.global [%0], [%1], 16;\n"
                 :: "r"(saddr), "l"(gaddr));
}
__device__ __forceinline__ void cpa_commit() { asm volatile("cp.async.commit_group;\n"); }
__device__ __forceinline__ void cpa_wait1()  { asm volatile("cp.async.wait_group 1;\n"); }

// ===========================================================================
// FAST kernel. Requirements (all call sites satisfy):
//   A k-contiguous, M % 128 == 0, K % 16 == 0, N % TBN == 0.
//   BTR=1: B n-contiguous (row stride ldb along k).  BTR=0: B k-contiguous.
//   CVA/CVB: convert operand to tf32 at fragment load (0 when the producer
//   already stored tf32-rounded values — bit-identical results).
// 3-stage cp.async pipeline, 128 x TBN tile, BK=16, 256 threads.
// ===========================================================================
#define SK 20   /* A / B(ldsm) smem row stride in u32 */

template<int TBN, int BTR, int CVA, int CVB>
__global__ __launch_bounds__(256, 2) void gemm_fast(
    const float* __restrict__ A, const float* __restrict__ B,
    float* __restrict__ C, int K,
    long ldaI, long bsA,
    long ldb,  long bsB,
    long ldcI, long bsC,
    const float* __restrict__ bias, int act, int diagskip, int rndC,
    float* __restrict__ C2, const float* __restrict__ bias2)
{
    constexpr int WARPS_M = (TBN == 128) ? 2 : 4;
    constexpr int MT      = (128 / WARPS_M) / 16;     // 4 / 2
    constexpr int NT      = 4;                        // warp covers 32 cols
    constexpr int NCHB    = TBN / 64;                 // B chunks per thread
    constexpr int BSTR    = BTR ? (TBN + 8) : SK;     // B smem row stride (u32)
    constexpr int ABUF    = 128 * SK * 4;             // bytes per A stage
    constexpr int BBUF    = (BTR ? 16 * BSTR : TBN * SK) * 4;

    extern __shared__ __align__(16) u32 dyn[];
    u32* Asp = dyn;                    // [3][128][SK]
    u32* Bsp = dyn + 3 * 128 * SK;     // [3][...]

    const int i0 = blockIdx.y * 128;
    const int j0 = blockIdx.x * TBN;
    if (diagskip && (i0 + j0 < 770 || i0 + j0 > 2047)) return;

    const int z = blockIdx.z;
    const float* Ab = A + (long)z * bsA;
    const float* Bb = B + (long)z * bsB;
    float*       Cb = C + (long)z * bsC;

    const int tid  = threadIdx.x;
    const int warp = tid >> 5;
    const int lane = tid & 31;
    const int g = lane >> 2;
    const int t = lane & 3;
    const int wm = (warp % WARPS_M) * (128 / WARPS_M);
    const int wn = (warp / WARPS_M) * 32;

    const u32 sa_base = (u32)__cvta_generic_to_shared(Asp);
    const u32 sb_base = (u32)__cvta_generic_to_shared(Bsp);

    // ---- fragment addresses (loop-invariant) ----
    const int mi = lane >> 3;
    const int ri = lane & 7;
    u32 aoff[MT];
#pragma unroll
    for (int mt = 0; mt < MT; mt++)
        aoff[mt] = ((u32)(wm + mt * 16 + (mi & 1) * 8 + ri) * SK + (u32)(mi >> 1) * 4) * 4;
    u32 boff[2];
#pragma unroll
    for (int p = 0; p < 2; p++)
        boff[p] = ((u32)(wn + p * 16 + (mi >> 1) * 8 + ri) * SK + (u32)(mi & 1) * 4) * 4;

    // ---- staging descriptors ----
    const int arow = tid >> 2;
    const int aq4  = (tid & 3) * 4;
    u32 sAo[2];
    const float* gA[2];
    sAo[0] = ((u32)arow * SK + aq4) * 4;
    sAo[1] = ((u32)(arow + 64) * SK + aq4) * 4;
    gA[0] = Ab + (long)(i0 + arow) * ldaI + aq4;
    gA[1] = Ab + (long)(i0 + arow + 64) * ldaI + aq4;

    u32 sBo[NCHB];
    const float* gB[NCHB];
    long bstep;
    if (BTR) {
        bstep = 16 * ldb;
#pragma unroll
        for (int u = 0; u < NCHB; u++) {
            int idx = tid + 256 * u;
            int k  = idx / (TBN / 4);
            int n4 = (idx % (TBN / 4)) * 4;
            sBo[u] = ((u32)k * BSTR + n4) * 4;
            gB[u]  = Bb + (long)k * ldb + (j0 + n4);
        }
    } else {
        bstep = 16;
#pragma unroll
        for (int u = 0; u < NCHB; u++) {
            int idx = tid + 256 * u;
            int n  = idx >> 2;
            int q4 = (idx & 3) * 4;
            sBo[u] = ((u32)n * SK + q4) * 4;
            gB[u]  = Bb + (long)(j0 + n) * ldb + q4;
        }
    }

    const int nk = K >> 4;

    auto issue = [&](int stage, int it) {
        u32 ab = sa_base + (u32)stage * ABUF;
        u32 bb = sb_base + (u32)stage * BBUF;
        long ka = (long)it * 16;
        long kb = (long)it * bstep;
        cpa16(ab + sAo[0], gA[0] + ka);
        cpa16(ab + sAo[1], gA[1] + ka);
#pragma unroll
        for (int u = 0; u < NCHB; u++)
            cpa16(bb + sBo[u], gB[u] + kb);
    };

    float acc[MT][NT][4];
#pragma unroll
    for (int mt = 0; mt < MT; mt++)
#pragma unroll
        for (int nt = 0; nt < NT; nt++)
#pragma unroll
            for (int e = 0; e < 4; e++) acc[mt][nt][e] = 0.0f;

    // prologue
    issue(0, 0); cpa_commit();
    if (nk > 1) issue(1, 1);
    cpa_commit();

    int buf = 0;
    for (int it = 0; it < nk; it++) {
        cpa_wait1();
        __syncthreads();

        const u32 ab = sa_base + (u32)buf * ABUF;
        const u32 bb = sb_base + (u32)buf * BBUF;
        const u32* Brow = Bsp + buf * (BBUF / 4);

#pragma unroll
        for (int kk = 0; kk < 2; kk++) {
            const u32 ksb = kk * 32;
            const int ks  = kk * 8;
            u32 af[MT][4], bf2[2][4];
#pragma unroll
            for (int mt = 0; mt < MT; mt++) {
                ldsm4(af[mt][0], af[mt][1], af[mt][2], af[mt][3], ab + aoff[mt] + ksb);
                if (CVA) {
                    af[mt][0] = cvtu(af[mt][0]); af[mt][1] = cvtu(af[mt][1]);
                    af[mt][2] = cvtu(af[mt][2]); af[mt][3] = cvtu(af[mt][3]);
                }
            }
            if (BTR) {
#pragma unroll
                for (int p = 0; p < 2; p++) {
                    int c = wn + p * 16;
                    bf2[p][0] = Brow[(ks + t) * BSTR + c + g];
                    bf2[p][1] = Brow[(ks + t + 4) * BSTR + c + g];
                    bf2[p][2] = Brow[(ks + t) * BSTR + c + 8 + g];
                    bf2[p][3] = Brow[(ks + t + 4) * BSTR + c + 8 + g];
                    if (CVB) {
                        bf2[p][0] = cvtu(bf2[p][0]); bf2[p][1] = cvtu(bf2[p][1]);
                        bf2[p][2] = cvtu(bf2[p][2]); bf2[p][3] = cvtu(bf2[p][3]);
                    }
                }
            } else {
#pragma unroll
                for (int p = 0; p < 2; p++) {
                    ldsm4(bf2[p][0], bf2[p][1], bf2[p][2], bf2[p][3], bb + boff[p] + ksb);
                    if (CVB) {
                        bf2[p][0] = cvtu(bf2[p][0]); bf2[p][1] = cvtu(bf2[p][1]);
                        bf2[p][2] = cvtu(bf2[p][2]); bf2[p][3] = cvtu(bf2[p][3]);
                    }
                }
            }
#pragma unroll
            for (int mt = 0; mt < MT; mt++)
#pragma unroll
                for (int nt = 0; nt < NT; nt++)
                    mma_tf32(acc[mt][nt], af[mt], &bf2[nt >> 1][(nt & 1) * 2]);
        }

        int ns = it + 2;
        if (ns < nk) issue(ns >= 3 ? ns - 3 * (ns / 3) : ns, ns);  // stage = ns % 3
        cpa_commit();
        buf = (buf == 2) ? 0 : buf + 1;
    }

    // epilogue
#pragma unroll
    for (int mt = 0; mt < MT; mt++) {
#pragma unroll
        for (int nt = 0; nt < NT; nt++) {
            int col = j0 + wn + nt * 8 + t * 2;
            float b0 = 0.0f, b1 = 0.0f;
            if (bias) { b0 = bias[col]; b1 = bias[col + 1]; }
            float c0 = 0.0f, c1 = 0.0f;
            if (C2) { c0 = bias2[col]; c1 = bias2[col + 1]; }
#pragma unroll
            for (int half = 0; half < 2; half++) {
                int row = i0 + wm + mt * 16 + g + half * 8;
                float a0 = acc[mt][nt][half * 2 + 0];
                float a1 = acc[mt][nt][half * 2 + 1];
                float v0 = a0 + b0, v1 = a1 + b1;
                if (act) {
                    v0 = 0.5f * v0 * (1.0f + erff(v0 * 0.70710678118654752f));
                    v1 = 0.5f * v1 * (1.0f + erff(v1 * 0.70710678118654752f));
                }
                if (rndC) { v0 = tf32r(v0); v1 = tf32r(v1); }
                *(float2*)&Cb[(long)row * ldcI + col] = make_float2(v0, v1);
                if (C2) {
                    float w0 = a0 + c0, w1 = a1 + c1;
                    if (rndC) { w0 = tf32r(w0); w1 = tf32r(w1); }
                    *(float2*)&C2[(long)row * ldcI + col] = make_float2(w0, w1);
                }
            }
        }
    }
}

// ===========================================================================
// Generic fallback — used only for the two target-mapping GEMMs.
// ===========================================================================
#define BM 128
#define BN 64
#define BKT 16

__global__ __launch_bounds__(256) void bgemm_tc(
    const float* __restrict__ A, const float* __restrict__ B,
    float* __restrict__ C,
    int M, int N, int K,
    long ldaI, long ldaK, long bsA,
    long ldbK, long ldbJ, long bsB,
    long ldcI, long bsC)
{
    __shared__ u32 As[2][BM][BKT + 1];
    __shared__ u32 Bs[2][BN][BKT + 1];

    const int z = blockIdx.z;
    const float* Ab = A + (long)z * bsA;
    const float* Bb = B + (long)z * bsB;
    float*       Cb = C + (long)z * bsC;

    const int i0 = blockIdx.y * BM;
    const int j0 = blockIdx.x * BN;
    const int tid  = threadIdx.x;
    const int warp = tid >> 5;
    const int lane = tid & 31;
    const int g = lane >> 2;
    const int t = lane & 3;
    const int wm = (warp & 3) * 32;
    const int wn = (warp >> 2) * 32;

    const bool ak1 = (ldaK == 1);
    const bool bj1 = (ldbJ == 1);

    float acc[2][4][4];
#pragma unroll
    for (int mt = 0; mt < 2; mt++)
#pragma unroll
        for (int nt = 0; nt < 4; nt++)
#pragma unroll
            for (int e = 0; e < 4; e++) acc[mt][nt][e] = 0.0f;

    float ra[8], rb[4];

    auto stage = [&](int k0) {
#pragma unroll
        for (int u = 0; u < 8; u++) {
            int e = tid + u * 256;
            int i, k;
            if (ak1) { k = e & 15; i = e >> 4; }
            else     { i = e & 127; k = e >> 7; }
            int gi = i0 + i, gk = k0 + k;
            ra[u] = (gi < M && gk < K) ? Ab[(long)gi * ldaI + (long)gk * ldaK] : 0.0f;
        }
#pragma unroll
        for (int u = 0; u < 4; u++) {
            int e = tid + u * 256;
            int n, k;
            if (bj1) { n = e & 63; k = e >> 6; }
            else     { k = e & 15; n = e >> 4; }
            int gn = j0 + n, gk = k0 + k;
            rb[u] = (gn < N && gk < K) ? Bb[(long)gk * ldbK + (long)gn * ldbJ] : 0.0f;
        }
    };
    auto commit = [&](int buf) {
#pragma unroll
        for (int u = 0; u < 8; u++) {
            int e = tid + u * 256;
            int i, k;
            if (ak1) { k = e & 15; i = e >> 4; }
            else     { i = e & 127; k = e >> 7; }
            As[buf][i][k] = f2tf32(ra[u]);
        }
#pragma unroll
        for (int u = 0; u < 4; u++) {
            int e = tid + u * 256;
            int n, k;
            if (bj1) { n = e & 63; k = e >> 6; }
            else     { k = e & 15; n = e >> 4; }
            Bs[buf][n][k] = f2tf32(rb[u]);
        }
    };

    stage(0);
    commit(0);
    __syncthreads();

    int buf = 0;
    for (int k0 = 0; k0 < K; k0 += BKT) {
        const bool more = (k0 + BKT) < K;
        if (more) stage(k0 + BKT);

#pragma unroll
        for (int kk = 0; kk < 2; kk++) {
            const int ks = kk * 8;
            u32 af[2][4], bf[4][2];
#pragma unroll
            for (int mt = 0; mt < 2; mt++) {
                int r = wm + mt * 16;
                af[mt][0] = As[buf][r + g    ][ks + t];
                af[mt][1] = As[buf][r + g + 8][ks + t];
                af[mt][2] = As[buf][r + g    ][ks + t + 4];
                af[mt][3] = As[buf][r + g + 8][ks + t + 4];
            }
#pragma unroll
            for (int nt = 0; nt < 4; nt++) {
                int c = wn + nt * 8;
                bf[nt][0] = Bs[buf][c + g][ks + t];
                bf[nt][1] = Bs[buf][c + g][ks + t + 4];
            }
#pragma unroll
            for (int mt = 0; mt < 2; mt++)
#pragma unroll
                for (int nt = 0; nt < 4; nt++)
                    mma_tf32(acc[mt][nt], af[mt], bf[nt]);
        }

        if (more) {
            commit(buf ^ 1);
            __syncthreads();
            buf ^= 1;
        }
    }

#pragma unroll
    for (int mt = 0; mt < 2; mt++) {
#pragma unroll
        for (int nt = 0; nt < 4; nt++) {
            int col = j0 + wn + nt * 8 + t * 2;
            if (col >= N) continue;
#pragma unroll
            for (int half = 0; half < 2; half++) {
                int row = i0 + wm + mt * 16 + g + half * 8;
                if (row >= M) continue;
                *(float2*)&Cb[(long)row * ldcI + col] =
                    make_float2(acc[mt][nt][half * 2 + 0], acc[mt][nt][half * 2 + 1]);
            }
        }
    }
}

// ---------------------------------------------------------------------------
// QW/QR = tf32round(src + bias)  (outputs consumed only as GEMM operands)
// ---------------------------------------------------------------------------
__global__ void add_bias2(const float* __restrict__ src,
                          const float* __restrict__ bw,
                          const float* __restrict__ br,
                          float* __restrict__ dw, float* __restrict__ dr, long n)
{
    long idx = (long)blockIdx.x * blockDim.x + threadIdx.x;
    long stride = (long)gridDim.x * blockDim.x;
    for (; idx < n; idx += stride) {
        int c = (int)(idx & (DM - 1));
        float v = src[idx];
        dw[idx] = tf32r(v + bw[c]);
        dr[idx] = tf32r(v + br[c]);
    }
}

// ---------------------------------------------------------------------------
// Softmax with relative shift gather; stores tf32-rounded P (only consumed
// by the P@V GEMM).
// ---------------------------------------------------------------------------
__global__ void softmax_shift(const float* __restrict__ AC,
                              const float* __restrict__ BD,
                              const float* __restrict__ mask,
                              float* __restrict__ P)
{
    const int i = blockIdx.x;
    const int z = blockIdx.y;
    const int b = z >> 4;
    const float* ac = AC + ((long)z * QLEN + i) * KLEN;
    const float* bd = BD + ((long)z * QLEN + i) * RLEN;
    float*       p  = P  + ((long)z * QLEN + i) * KLEN;

    __shared__ float red[256];
    const int tid = threadIdx.x;

    float vals[4];
    float lm = -1e38f;
#pragma unroll
    for (int r = 0; r < 4; r++) {
        int j = tid + r * 256;
        float s = (ac[j] + bd[j - i + KLEN]) * 0.125f
                - 1e30f * mask[((long)i * KLEN + j) * BSZ + b];
        vals[r] = s;
        lm = fmaxf(lm, s);
    }
    red[tid] = lm; __syncthreads();
    for (int s = 128; s > 0; s >>= 1) {
        if (tid < s) red[tid] = fmaxf(red[tid], red[tid + s]);
        __syncthreads();
    }
    float mx = red[0]; __syncthreads();

    float ls = 0.0f;
#pragma unroll
    for (int r = 0; r < 4; r++) {
        vals[r] = __expf(vals[r] - mx);
        ls += vals[r];
    }
    red[tid] = ls; __syncthreads();
    for (int s = 128; s > 0; s >>= 1) {
        if (tid < s) red[tid] += red[tid + s];
        __syncthreads();
    }
    float inv = 1.0f / red[0];
#pragma unroll
    for (int r = 0; r < 4; r++)
        p[tid + r * 256] = tf32r(vals[r] * inv);
}

// ---------------------------------------------------------------------------
__global__ void ln_res(const float* __restrict__ x, const float* __restrict__ res,
                       const float* __restrict__ sc, const float* __restrict__ bi,
                       float* __restrict__ out)
{
    const long row = blockIdx.x;
    const float* xr = x   + row * DM;
    const float* rr = res + row * DM;
    float*       o  = out + row * DM;
    const int tid = threadIdx.x;

    __shared__ float red[256];

    float v[4];
    float s = 0.0f;
#pragma unroll
    for (int r = 0; r < 4; r++) {
        int c = tid + r * 256;
        v[r] = xr[c] + rr[c];
        s += v[r];
    }
    red[tid] = s; __syncthreads();
    for (int st = 128; st > 0; st >>= 1) {
        if (tid < st) red[tid] += red[tid + st];
        __syncthreads();
    }
    float mean = red[0] * (1.0f / DM); __syncthreads();

    float sq = 0.0f;
#pragma unroll
    for (int r = 0; r < 4; r++) {
        float d = v[r] - mean;
        sq += d * d;
    }
    red[tid] = sq; __syncthreads();
    for (int st = 128; st > 0; st >>= 1) {
        if (tid < st) red[tid] += red[tid + st];
        __syncthreads();
    }
    float rstd = rsqrtf(red[0] * (1.0f / DM) + 1e-8f);
#pragma unroll
    for (int r = 0; r < 4; r++) {
        int c = tid + r * 256;
        o[c] = (v[r] - mean) * rstd * sc[c] + bi[c];
    }
}

// ---------------------------------------------------------------------------
template<int TBN, int BTR, int CVA, int CVB>
static void launchG(const float* A, const float* B, float* C,
                    int M, int N, int K,
                    long ldaI, long bsA, long ldb, long bsB,
                    long ldcI, long bsC,
                    const float* bias, int act, int nb,
                    int diagskip = 0, int rndC = 0,
                    float* C2 = nullptr, const float* bias2 = nullptr)
{
    constexpr int BSTR = BTR ? (TBN + 8) : SK;
    constexpr int SMEM = (3 * 128 * SK + 3 * (BTR ? 16 * BSTR : TBN * SK)) * 4;
    cudaFuncSetAttribute(gemm_fast<TBN, BTR, CVA, CVB>,
                         cudaFuncAttributeMaxDynamicSharedMemorySize, SMEM);
    gemm_fast<TBN, BTR, CVA, CVB><<<dim3(N / TBN, M / 128, nb), 256, SMEM>>>(
        A, B, C, K, ldaI, bsA, ldb, bsB, ldcI, bsC, bias, act, diagskip, rndC, C2, bias2);
}

extern "C" void kernel_launch(void* const* d_in, const int* in_sizes, int n_in,
                              void* d_out, int out_size)
{
    const float* Xh  = (const float*)d_in[0];
    const float* Xg  = (const float*)d_in[1];
    const float* mh  = (const float*)d_in[2];
    const float* mg  = (const float*)d_in[3];
    const float* R   = (const float*)d_in[4];
    const float* TM  = (const float*)d_in[5];
    const float* qw  = (const float*)d_in[6];
    const float* kw  = (const float*)d_in[7];
    const float* vw  = (const float*)d_in[8];
    const float* rw  = (const float*)d_in[9];
    const float* rrb = (const float*)d_in[10];
    const float* rwb = (const float*)d_in[11];
    const float* lns = (const float*)d_in[12];
    const float* lnb = (const float*)d_in[13];
    const float* w1  = (const float*)d_in[14];
    const float* b1  = (const float*)d_in[15];
    const float* w2  = (const float*)d_in[16];
    const float* b2  = (const float*)d_in[17];
    const float* fls = (const float*)d_in[18];
    const float* flb = (const float*)d_in[19];
    float* out = (float*)d_out;

    float *KH, *VH, *KR, *QT, *QW, *QR, *QG, *AC, *BD, *AV, *AV2,
          *ATTH, *ATTG, *FF1, *FF2;
    cudaGetSymbolAddress((void**)&KH,  g_KH);
    cudaGetSymbolAddress((void**)&VH,  g_VH);
    cudaGetSymbolAddress((void**)&KR,  g_KR);
    cudaGetSymbolAddress((void**)&QT,  g_QT);
    cudaGetSymbolAddress((void**)&QW,  g_QW);
    cudaGetSymbolAddress((void**)&QR,  g_QR);
    cudaGetSymbolAddress((void**)&QG,  g_QG);
    cudaGetSymbolAddress((void**)&AC,  g_AC);
    cudaGetSymbolAddress((void**)&BD,  g_BD);
    cudaGetSymbolAddress((void**)&AV,  g_AV);
    cudaGetSymbolAddress((void**)&AV2, g_AV2);
    cudaGetSymbolAddress((void**)&ATTH, g_ATTH);
    cudaGetSymbolAddress((void**)&ATTG, g_ATTG);
    cudaGetSymbolAddress((void**)&FF1, g_FF1);
    cudaGetSymbolAddress((void**)&FF2, g_FF2);

    const int T = 256;
    const int MH = QLEN * BSZ;     // 4096
    const int MG = NPRED * BSZ;    // 1024

    // ---- shared projections (inputs full fp32 -> cvt; outputs tf32-rounded) ----
    launchG<128,1,1,1>(Xh, kw, KH, MH, DM, DM, DM, 0, DM, 0, DM, 0, nullptr, 0, 1, 0, 1);
    launchG<128,1,1,1>(Xh, vw, VH, MH, DM, DM, DM, 0, DM, 0, DM, 0, nullptr, 0, 1, 0, 1);
    launchG<128,1,1,1>(R,  rw, KR, RLEN * BSZ, DM, DM, DM, 0, DM, 0, DM, 0, nullptr, 0, 1, 0, 1);

    // ================= h-stream =================
    // fused Q projection: QW = rnd(Xh@qw + r_w_bias), QR = rnd(Xh@qw + r_r_bias)
    launchG<128,1,1,1>(Xh, qw, QW, MH, DM, DM, DM, 0, DM, 0, DM, 0, rwb, 0, 1, 0, 1, QR, rrb);

    launchG<128,0,0,0>(QW, KH, AC, QLEN, KLEN, DH, 4096, 64, 4096, 64,
                   KLEN, (long)QLEN * KLEN, nullptr, 0, NB);
    launchG<128,0,0,0>(QR, KR, BD, QLEN, RLEN, DH, 4096, 64, 4096, 64,
                   RLEN, (long)QLEN * RLEN, nullptr, 0, NB, 1);
    softmax_shift<<<dim3(QLEN, NB), T>>>(AC, BD, mh, AC);
    launchG<64,1,0,0>(AC, VH, AV, QLEN, DH, KLEN, KLEN, (long)QLEN * KLEN,
                  4096, 64, 4096, 64, nullptr, 0, NB);
    ln_res<<<MH, T>>>(AV, Xh, lns, lnb, ATTH);

    // ================= g-stream =================
    launchG<128,1,1,1>(Xg, qw, QG, MG, DM, DM, DM, 0, DM, 0, DM, 0, nullptr, 0, 1);
    bgemm_tc<<<dim3(DM / BN, QLEN / BM, BSZ), T>>>(TM, QG, QT, QLEN, DM, NPRED,
              4, 4096, 1,   4096, 1, DM,   4096, DM);
    add_bias2<<<4096, T>>>(QT, rwb, rrb, QW, QR, (long)MH * DM);

    launchG<128,0,0,0>(QW, KH, AC, QLEN, KLEN, DH, 4096, 64, 4096, 64,
                   KLEN, (long)QLEN * KLEN, nullptr, 0, NB);
    launchG<128,0,0,0>(QR, KR, BD, QLEN, RLEN, DH, 4096, 64, 4096, 64,
                   RLEN, (long)QLEN * RLEN, nullptr, 0, NB, 1);
    softmax_shift<<<dim3(QLEN, NB), T>>>(AC, BD, mg, AC);
    launchG<64,1,0,0>(AC, VH, AV, QLEN, DH, KLEN, KLEN, (long)QLEN * KLEN,
                  4096, 64, 4096, 64, nullptr, 0, NB);
    bgemm_tc<<<dim3(DM / BN, NPRED / BM, BSZ), T>>>(TM, AV, AV2, NPRED, DM, QLEN,
              4096, 4, 1,   4096, 1, DM,   4096, DM);
    ln_res<<<MG, T>>>(AV2, Xg, lns, lnb, ATTG);

    // ================= FFN (h) =================
    launchG<128,1,1,1>(ATTH, w1, FF1, MH, DI, DM, DM, 0, DI, 0, DI, 0, b1, 1, 1, 0, 1);
    launchG<128,1,0,1>(FF1, w2, FF2, MH, DM, DI, DI, 0, DM, 0, DM, 0, b2, 0, 1);
    ln_res<<<MH, T>>>(FF2, ATTH, fls, flb, out);

    // ================= FFN (g) =================
    launchG<128,1,1,1>(ATTG, w1, FF1, MG, DI, DM, DM, 0, DI, 0, DI, 0, b1, 1, 1, 0, 1);
    launchG<128,1,0,1>(FF1, w2, FF2, MG, DM, DI, DI, 0, DM, 0, DM, 0, b2, 0, 1);
    ln_res<<<MG, T>>>(FF2, ATTG, fls, flb, out + (long)MH * DM);
}